// round 14
// baseline (speedup 1.0000x reference)
#include <cuda_runtime.h>
#include <cuda_bf16.h>
#include <cuda_fp16.h>
#include <math.h>
#include <stdint.h>

// Problem constants
#define NN     20000
#define EE     400000
#define ETOT   420000
#define INC    768
#define HID    128
#define HEADS  4
#define FMAX   512

// ---------------- device scratch ----------------
__device__ __half g_hlin[(size_t)NN * FMAX];
__device__ float g_asrc[(size_t)NN * HEADS];
__device__ float g_adst[(size_t)NN * HEADS];
__device__ __nv_bfloat16 g_ah [(size_t)NN * INC];
__device__ __nv_bfloat16 g_al [(size_t)NN * INC];
__device__ __nv_bfloat16 g_wth[(size_t)FMAX * INC];
__device__ __nv_bfloat16 g_wtl[(size_t)FMAX * INC];
__device__ int g_deg[NN];
__device__ int g_cur[NN];
__device__ int g_rowptr[NN + 1];
__device__ int g_esrc[ETOT];

// ---------------- misc helpers ----------------
__device__ __forceinline__ int clampN(int v) { return v < 0 ? 0 : (v >= NN ? NN - 1 : v); }
__device__ __forceinline__ uint32_t smem_u32(const void* p) {
    uint32_t a;
    asm("{ .reg .u64 t; cvta.to.shared.u64 t, %1; cvt.u32.u64 %0, t; }" : "=r"(a) : "l"(p));
    return a;
}

__global__ void zero_int2_kernel(int* __restrict__ a, int* __restrict__ b, int n) {
    int i = blockIdx.x * blockDim.x + threadIdx.x;
    if (i < n) { a[i] = 0; b[i] = 0; }
}
__global__ void zero_f2_kernel(float* __restrict__ a, float* __restrict__ b, int n) {
    int i = blockIdx.x * blockDim.x + threadIdx.x;
    if (i < n) { a[i] = 0.f; b[i] = 0.f; }
}

// ---------------- CSR build ----------------
__global__ void count_kernel(const int* __restrict__ ei, int* __restrict__ deg) {
    int e = blockIdx.x * blockDim.x + threadIdx.x;
    if (e >= ETOT) return;
    int d = (e < EE) ? clampN(ei[EE + e]) : e - EE;
    atomicAdd(&deg[d], 1);
}

#define SCAN_T 1024
#define SCAN_CH 20
__global__ void scan_kernel(const int* __restrict__ deg, int* __restrict__ rowptr) {
    __shared__ int sums[SCAN_T];
    int t = threadIdx.x;
    int base = t * SCAN_CH;
    int local = 0;
#pragma unroll
    for (int i = 0; i < SCAN_CH; i++) {
        int idx = base + i;
        if (idx < NN) local += deg[idx];
    }
    sums[t] = local;
    __syncthreads();
    for (int off = 1; off < SCAN_T; off <<= 1) {
        int v = (t >= off) ? sums[t - off] : 0;
        __syncthreads();
        sums[t] += v;
        __syncthreads();
    }
    int run = sums[t] - local;
#pragma unroll
    for (int i = 0; i < SCAN_CH; i++) {
        int idx = base + i;
        if (idx < NN) { rowptr[idx] = run; run += deg[idx]; }
    }
    if (t == SCAN_T - 1) rowptr[NN] = sums[SCAN_T - 1];
}

__global__ void scatter_kernel(const int* __restrict__ ei,
                               const int* __restrict__ rowptr,
                               int* __restrict__ cur, int* __restrict__ esrc) {
    int e = blockIdx.x * blockDim.x + threadIdx.x;
    if (e >= ETOT) return;
    int s, d;
    if (e < EE) { s = clampN(ei[e]); d = clampN(ei[EE + e]); } else { s = d = e - EE; }
    int pos = rowptr[d] + atomicAdd(&cur[d], 1);
    esrc[pos] = s;
}

// ---------------- fp32 -> bf16 hi/lo split (x only) ----------------
__global__ void split_kernel(const float* __restrict__ x,
                             __nv_bfloat16* __restrict__ hi,
                             __nv_bfloat16* __restrict__ lo, int n) {
    int i = blockIdx.x * blockDim.x + threadIdx.x;
    if (i >= n) return;
    float v = x[i];
    __nv_bfloat16 h = __float2bfloat16(v);
    hi[i] = h;
    lo[i] = __float2bfloat16(v - __bfloat162float(h));
}

// W [K,N] fp32 -> Wt hi/lo [N,K] bf16 via smem-tiled transpose
__global__ void splitT_kernel(const float* __restrict__ W,
                              __nv_bfloat16* __restrict__ hi,
                              __nv_bfloat16* __restrict__ lo, int K, int Nn) {
    __shared__ float t[32][33];
    const int tx = threadIdx.x;
    const int ty = threadIdx.y;
    const int n0 = blockIdx.x * 32;
    const int k0 = blockIdx.y * 32;
#pragma unroll
    for (int i = 0; i < 4; i++) {
        int k = k0 + ty + i * 8;
        t[ty + i * 8][tx] = W[(size_t)k * Nn + n0 + tx];
    }
    __syncthreads();
#pragma unroll
    for (int i = 0; i < 4; i++) {
        int n = n0 + ty + i * 8;
        float v = t[tx][ty + i * 8];
        __nv_bfloat16 h = __float2bfloat16(v);
        size_t o = (size_t)n * K + k0 + tx;
        hi[o] = h;
        lo[o] = __float2bfloat16(v - __bfloat162float(h));
    }
}

// ---------------- HMMA bf16 GEMM: BK=32, 2-stage cp.async, 1 barrier/chunk --
#define SPAD 40
#define TILE_ELEMS (128 * SPAD)
#define STAGE_ELEMS (4 * TILE_ELEMS)
#define GEMM_SMEM (2 * STAGE_ELEMS * 2)   // 81920 bytes

__device__ __forceinline__ void mma_bf16(float* c, const uint32_t* a, const uint32_t* b) {
    asm volatile("mma.sync.aligned.m16n8k16.row.col.f32.bf16.bf16.f32 "
                 "{%0,%1,%2,%3}, {%4,%5,%6,%7}, {%8,%9}, {%0,%1,%2,%3};"
                 : "+f"(c[0]), "+f"(c[1]), "+f"(c[2]), "+f"(c[3])
                 : "r"(a[0]), "r"(a[1]), "r"(a[2]), "r"(a[3]),
                   "r"(b[0]), "r"(b[1]));
}
#define LDM_X4(r0, r1, r2, r3, a) \
    asm volatile("ldmatrix.sync.aligned.m8n8.x4.shared.b16 {%0,%1,%2,%3}, [%4];" \
                 : "=r"(r0), "=r"(r1), "=r"(r2), "=r"(r3) : "r"(a))
#define CP_ASYNC16(dst, src) \
    asm volatile("cp.async.cg.shared.global [%0], [%1], 16;" :: "r"(dst), "l"(src))

template <int H>
__global__ void __launch_bounds__(256)
hgemm_kernel(const __nv_bfloat16* __restrict__ Ah,
             const __nv_bfloat16* __restrict__ Al,
             const __nv_bfloat16* __restrict__ Bh,
             const __nv_bfloat16* __restrict__ Bl,
             __half* __restrict__ C,
             const float* __restrict__ avec_src,
             const float* __restrict__ avec_dst,
             float* __restrict__ asrc,
             float* __restrict__ adst,
             int M, int K, int Nn) {
    extern __shared__ __nv_bfloat16 sm[];

    const int tid  = threadIdx.x;
    const int lane = tid & 31;
    const int wid  = tid >> 5;
    const int wm   = (wid >> 2) * 64;
    const int wn   = (wid & 3) * 32;
    const int row0 = blockIdx.y * 128;
    const int col0 = blockIdx.x * 128;
    const int g4   = lane >> 2;
    const int t4   = lane & 3;

    const int a_off = (lane & 15) * SPAD + (lane >> 4) * 8;
    const int b_off = ((lane & 7) + ((lane & 16) ? 8 : 0)) * SPAD + ((lane & 8) ? 8 : 0);

    const int lr = tid >> 1;
    const int lc = (tid & 1) * 16;

    float acc[4][4][4];
#pragma unroll
    for (int a = 0; a < 4; a++)
#pragma unroll
        for (int b = 0; b < 4; b++)
#pragma unroll
            for (int c = 0; c < 4; c++) acc[a][b][c] = 0.f;

    const int nCh = K >> 5;
    const int gra = min(row0 + lr, M - 1);
    const int grb = col0 + lr;
    const uint32_t smb = smem_u32(sm);

#define ISSUE(ch) do {                                                          \
    uint32_t sb_ = smb + (uint32_t)((ch) & 1) * (STAGE_ELEMS * 2);              \
    int kc0_ = (ch) << 5;                                                       \
    uint32_t d_ = sb_ + (uint32_t)(lr * SPAD + lc) * 2;                         \
    const __nv_bfloat16* pa_ = Ah + (size_t)gra * K + kc0_ + lc;                \
    const __nv_bfloat16* pb_ = Al + (size_t)gra * K + kc0_ + lc;                \
    const __nv_bfloat16* pc_ = Bh + (size_t)grb * K + kc0_ + lc;                \
    const __nv_bfloat16* pd_ = Bl + (size_t)grb * K + kc0_ + lc;                \
    CP_ASYNC16(d_ + 0 * TILE_ELEMS * 2,      pa_);                              \
    CP_ASYNC16(d_ + 0 * TILE_ELEMS * 2 + 16, pa_ + 8);                          \
    CP_ASYNC16(d_ + 1 * TILE_ELEMS * 2,      pb_);                              \
    CP_ASYNC16(d_ + 1 * TILE_ELEMS * 2 + 16, pb_ + 8);                          \
    CP_ASYNC16(d_ + 2 * TILE_ELEMS * 2,      pc_);                              \
    CP_ASYNC16(d_ + 2 * TILE_ELEMS * 2 + 16, pc_ + 8);                          \
    CP_ASYNC16(d_ + 3 * TILE_ELEMS * 2,      pd_);                              \
    CP_ASYNC16(d_ + 3 * TILE_ELEMS * 2 + 16, pd_ + 8);                          \
    asm volatile("cp.async.commit_group;");                                     \
} while (0)

    ISSUE(0);
    for (int ch = 0; ch < nCh; ch++) {
        asm volatile("cp.async.wait_group 0;");
        __syncthreads();
        // all warps have finished compute(ch-1): safe to overwrite its stage.
        if (ch + 1 < nCh) ISSUE(ch + 1);

        const uint32_t bAh = smb + (uint32_t)(ch & 1) * (STAGE_ELEMS * 2);
        const uint32_t bAl = bAh + TILE_ELEMS * 2;
        const uint32_t bBh = bAl + TILE_ELEMS * 2;
        const uint32_t bBl = bBh + TILE_ELEMS * 2;

#pragma unroll
        for (int ks = 0; ks < 32; ks += 16) {
            uint32_t bh[4][2], bl[4][2];
#pragma unroll
            for (int ntp = 0; ntp < 2; ntp++) {
                uint32_t off = (uint32_t)((wn + ntp * 16) * SPAD + ks + b_off) * 2;
                LDM_X4(bh[2 * ntp][0], bh[2 * ntp][1], bh[2 * ntp + 1][0], bh[2 * ntp + 1][1], bBh + off);
                LDM_X4(bl[2 * ntp][0], bl[2 * ntp][1], bl[2 * ntp + 1][0], bl[2 * ntp + 1][1], bBl + off);
            }
#pragma unroll
            for (int mt = 0; mt < 4; mt++) {
                uint32_t off = (uint32_t)((wm + mt * 16) * SPAD + ks + a_off) * 2;
                uint32_t ah[4], al[4];
                LDM_X4(ah[0], ah[1], ah[2], ah[3], bAh + off);
                LDM_X4(al[0], al[1], al[2], al[3], bAl + off);
#pragma unroll
                for (int nt = 0; nt < 4; nt++) {
                    mma_bf16(acc[mt][nt], ah, bh[nt]);
                    mma_bf16(acc[mt][nt], ah, bl[nt]);
                    mma_bf16(acc[mt][nt], al, bh[nt]);
                }
            }
        }
    }
#undef ISSUE

    // ---- epilogue: store C (fp16) + fused attention dots (fp32 regs) ----
    const int h = col0 >> 7;
    float vs[4][2], vd[4][2];
#pragma unroll
    for (int nt = 0; nt < 4; nt++) {
        int gc = col0 + wn + nt * 8 + t4 * 2;
#pragma unroll
        for (int j = 0; j < 2; j++) {
            vs[nt][j] = avec_src[gc + j];
            vd[nt][j] = avec_dst[gc + j];
        }
    }

#pragma unroll
    for (int mt = 0; mt < 4; mt++) {
        float ps0 = 0.f, pd0 = 0.f, ps1 = 0.f, pd1 = 0.f;
#pragma unroll
        for (int nt = 0; nt < 4; nt++) {
            int gm = row0 + wm + mt * 16 + g4;
            int gc = col0 + wn + nt * 8 + t4 * 2;
            if (gm < M)
                *(__half2*)&C[(size_t)gm * Nn + gc] =
                    __floats2half2_rn(acc[mt][nt][0], acc[mt][nt][1]);
            if (gm + 8 < M)
                *(__half2*)&C[(size_t)(gm + 8) * Nn + gc] =
                    __floats2half2_rn(acc[mt][nt][2], acc[mt][nt][3]);
            ps0 = fmaf(acc[mt][nt][0], vs[nt][0], fmaf(acc[mt][nt][1], vs[nt][1], ps0));
            pd0 = fmaf(acc[mt][nt][0], vd[nt][0], fmaf(acc[mt][nt][1], vd[nt][1], pd0));
            ps1 = fmaf(acc[mt][nt][2], vs[nt][0], fmaf(acc[mt][nt][3], vs[nt][1], ps1));
            pd1 = fmaf(acc[mt][nt][2], vd[nt][0], fmaf(acc[mt][nt][3], vd[nt][1], pd1));
        }
#pragma unroll
        for (int o = 1; o <= 2; o <<= 1) {
            ps0 += __shfl_xor_sync(0xffffffffu, ps0, o);
            pd0 += __shfl_xor_sync(0xffffffffu, pd0, o);
            ps1 += __shfl_xor_sync(0xffffffffu, ps1, o);
            pd1 += __shfl_xor_sync(0xffffffffu, pd1, o);
        }
        if (t4 == 0) {
            int gm = row0 + wm + mt * 16 + g4;
            if (gm < M) {
                atomicAdd(&asrc[(size_t)gm * H + h], ps0);
                atomicAdd(&adst[(size_t)gm * H + h], pd0);
            }
            if (gm + 8 < M) {
                atomicAdd(&asrc[(size_t)(gm + 8) * H + h], ps1);
                atomicAdd(&adst[(size_t)(gm + 8) * H + h], pd1);
            }
        }
    }
}

// ---------------- fused aggregate, H=4: one warp per NODE (all heads) -------
__global__ void aggregate4_kernel(const int* __restrict__ rowptr,
                                  const int* __restrict__ esrc,
                                  const float* __restrict__ asrc,
                                  const float* __restrict__ adst,
                                  const __half* __restrict__ hlin,
                                  const float* __restrict__ bias,
                                  __nv_bfloat16* __restrict__ hi,
                                  __nv_bfloat16* __restrict__ lo) {
    int n = (blockIdx.x * blockDim.x + threadIdx.x) >> 5;
    int lane = threadIdx.x & 31;
    if (n >= NN) return;
    float4 ad = *(const float4*)&adst[(size_t)n * 4];
    int beg = rowptr[n], end = rowptr[n + 1];

    float4 acc0 = {0,0,0,0}, acc1 = {0,0,0,0}, acc2 = {0,0,0,0}, acc3 = {0,0,0,0};
    float4 ss = {0,0,0,0};

    for (int base = beg; base < end; base += 32) {
        int j = base + lane;
        float4 vj = {0,0,0,0};
        int sj = 0;
        if (j < end) {
            sj = esrc[j];
            float4 as = *(const float4*)&asrc[(size_t)sj * 4];
            float e0 = as.x + ad.x, e1 = as.y + ad.y, e2 = as.z + ad.z, e3 = as.w + ad.w;
            e0 = (e0 > 0.f) ? e0 : 0.2f * e0;
            e1 = (e1 > 0.f) ? e1 : 0.2f * e1;
            e2 = (e2 > 0.f) ? e2 : 0.2f * e2;
            e3 = (e3 > 0.f) ? e3 : 0.2f * e3;
            vj.x = __expf(e0); vj.y = __expf(e1); vj.z = __expf(e2); vj.w = __expf(e3);
        }
        int cnt = min(32, end - base);
        for (int t = 0; t < cnt; t++) {
            int s   = __shfl_sync(0xffffffffu, sj, t);
            float w0 = __shfl_sync(0xffffffffu, vj.x, t);
            float w1 = __shfl_sync(0xffffffffu, vj.y, t);
            float w2 = __shfl_sync(0xffffffffu, vj.z, t);
            float w3 = __shfl_sync(0xffffffffu, vj.w, t);
            const uint2* p = (const uint2*)(hlin + (size_t)s * FMAX);
            uint2 u0 = p[lane];
            uint2 u1 = p[lane + 32];
            uint2 u2 = p[lane + 64];
            uint2 u3 = p[lane + 96];
            float2 a0 = __half22float2(*(const __half2*)&u0.x);
            float2 b0 = __half22float2(*(const __half2*)&u0.y);
            float2 a1 = __half22float2(*(const __half2*)&u1.x);
            float2 b1 = __half22float2(*(const __half2*)&u1.y);
            float2 a2 = __half22float2(*(const __half2*)&u2.x);
            float2 b2 = __half22float2(*(const __half2*)&u2.y);
            float2 a3 = __half22float2(*(const __half2*)&u3.x);
            float2 b3 = __half22float2(*(const __half2*)&u3.y);
            acc0.x = fmaf(w0, a0.x, acc0.x); acc0.y = fmaf(w0, a0.y, acc0.y);
            acc0.z = fmaf(w0, b0.x, acc0.z); acc0.w = fmaf(w0, b0.y, acc0.w);
            acc1.x = fmaf(w1, a1.x, acc1.x); acc1.y = fmaf(w1, a1.y, acc1.y);
            acc1.z = fmaf(w1, b1.x, acc1.z); acc1.w = fmaf(w1, b1.y, acc1.w);
            acc2.x = fmaf(w2, a2.x, acc2.x); acc2.y = fmaf(w2, a2.y, acc2.y);
            acc2.z = fmaf(w2, b2.x, acc2.z); acc2.w = fmaf(w2, b2.y, acc2.w);
            acc3.x = fmaf(w3, a3.x, acc3.x); acc3.y = fmaf(w3, a3.y, acc3.y);
            acc3.z = fmaf(w3, b3.x, acc3.z); acc3.w = fmaf(w3, b3.y, acc3.w);
            ss.x += w0; ss.y += w1; ss.z += w2; ss.w += w3;
        }
    }

#define FIN(acch, sh, hh) do {                                                  \
    float inv = 1.f / ((sh) + 1e-16f);                                          \
    float4 bv = *(const float4*)&bias[(hh) * HID + lane * 4];                   \
    float4 o;                                                                   \
    o.x = (acch).x * inv + bv.x;                                                \
    o.y = (acch).y * inv + bv.y;                                                \
    o.z = (acch).z * inv + bv.z;                                                \
    o.w = (acch).w * inv + bv.w;                                                \
    o.x = (o.x > 0.f) ? o.x : expm1f(o.x);                                      \
    o.y = (o.y > 0.f) ? o.y : expm1f(o.y);                                      \
    o.z = (o.z > 0.f) ? o.z : expm1f(o.z);                                      \
    o.w = (o.w > 0.f) ? o.w : expm1f(o.w);                                      \
    size_t off = ((size_t)n * 4 + (hh)) * HID + lane * 4;                       \
    __nv_bfloat16 hx = __float2bfloat16(o.x);                                   \
    __nv_bfloat16 hy = __float2bfloat16(o.y);                                   \
    __nv_bfloat16 hz = __float2bfloat16(o.z);                                   \
    __nv_bfloat16 hw = __float2bfloat16(o.w);                                   \
    hi[off + 0] = hx;  lo[off + 0] = __float2bfloat16(o.x - __bfloat162float(hx)); \
    hi[off + 1] = hy;  lo[off + 1] = __float2bfloat16(o.y - __bfloat162float(hy)); \
    hi[off + 2] = hz;  lo[off + 2] = __float2bfloat16(o.z - __bfloat162float(hz)); \
    hi[off + 3] = hw;  lo[off + 3] = __float2bfloat16(o.w - __bfloat162float(hw)); \
} while (0)

    FIN(acc0, ss.x, 0);
    FIN(acc1, ss.y, 1);
    FIN(acc2, ss.z, 2);
    FIN(acc3, ss.w, 3);
#undef FIN
}

// ---------------- fused aggregate H=1 (layer 3, fp32 out) -------------------
__global__ void aggregate1_kernel(const int* __restrict__ rowptr,
                                  const int* __restrict__ esrc,
                                  const float* __restrict__ asrc,
                                  const float* __restrict__ adst,
                                  const __half* __restrict__ hlin,
                                  const float* __restrict__ bias,
                                  float* __restrict__ out) {
    int n = (blockIdx.x * blockDim.x + threadIdx.x) >> 5;
    int lane = threadIdx.x & 31;
    if (n >= NN) return;
    float adn = adst[n];
    int beg = rowptr[n], end = rowptr[n + 1];

    float4 acc = {0,0,0,0};
    float ssum = 0.f;

    for (int base = beg; base < end; base += 32) {
        int j = base + lane;
        float vj = 0.f;
        int sj = 0;
        if (j < end) {
            sj = esrc[j];
            float v = asrc[sj] + adn;
            v = (v > 0.f) ? v : 0.2f * v;
            vj = __expf(v);
        }
        int cnt = min(32, end - base);
        for (int t = 0; t < cnt; t++) {
            float v = __shfl_sync(0xffffffffu, vj, t);
            int s   = __shfl_sync(0xffffffffu, sj, t);
            const uint2* hp = (const uint2*)(hlin + (size_t)s * HID);
            uint2 u = hp[lane];
            float2 f0 = __half22float2(*(const __half2*)&u.x);
            float2 f1 = __half22float2(*(const __half2*)&u.y);
            acc.x = fmaf(v, f0.x, acc.x);
            acc.y = fmaf(v, f0.y, acc.y);
            acc.z = fmaf(v, f1.x, acc.z);
            acc.w = fmaf(v, f1.y, acc.w);
            ssum += v;
        }
    }
    float inv = 1.f / (ssum + 1e-16f);
    float4 bv = *(const float4*)&bias[lane * 4];
    float4 o;
    o.x = acc.x * inv + bv.x;
    o.y = acc.y * inv + bv.y;
    o.z = acc.z * inv + bv.z;
    o.w = acc.w * inv + bv.w;
    *(float4*)&out[(size_t)n * HID + lane * 4] = o;
}

// ---------------- host orchestration ----------------
struct Buffers {
    __half* hlin;
    float *asrc, *adst;
    __nv_bfloat16 *ah, *al, *wth, *wtl;
    int *deg, *cur, *rowptr, *esrc;
};

template <int H>
static void run_gemm(int K, const float* W, const float* a_src, const float* a_dst,
                     const Buffers& B) {
    const int F = H * HID;
    dim3 tgrid(F / 32, K / 32);
    splitT_kernel<<<tgrid, dim3(32, 8)>>>(W, B.wth, B.wtl, K, F);
    int nh = NN * H;
    zero_f2_kernel<<<(nh + 255) / 256, 256>>>(B.asrc, B.adst, nh);
    dim3 grid(F / 128, (NN + 127) / 128);
    hgemm_kernel<H><<<grid, 256, GEMM_SMEM>>>(B.ah, B.al, B.wth, B.wtl, B.hlin,
                                              a_src, a_dst, B.asrc, B.adst, NN, K, F);
}

extern "C" void kernel_launch(void* const* d_in, const int* in_sizes, int n_in,
                              void* d_out, int out_size) {
    const float* x       = (const float*)d_in[0];
    const int*   ei      = (const int*)d_in[1];
    const float* W1      = (const float*)d_in[2];
    const float* a1_src  = (const float*)d_in[3];
    const float* a1_dst  = (const float*)d_in[4];
    const float* b1      = (const float*)d_in[5];
    const float* W2      = (const float*)d_in[6];
    const float* a2_src  = (const float*)d_in[7];
    const float* a2_dst  = (const float*)d_in[8];
    const float* b2      = (const float*)d_in[9];
    const float* W3      = (const float*)d_in[10];
    const float* a3_src  = (const float*)d_in[11];
    const float* a3_dst  = (const float*)d_in[12];
    const float* b3      = (const float*)d_in[13];

    Buffers B;
    cudaGetSymbolAddress((void**)&B.hlin,   g_hlin);
    cudaGetSymbolAddress((void**)&B.asrc,   g_asrc);
    cudaGetSymbolAddress((void**)&B.adst,   g_adst);
    cudaGetSymbolAddress((void**)&B.ah,     g_ah);
    cudaGetSymbolAddress((void**)&B.al,     g_al);
    cudaGetSymbolAddress((void**)&B.wth,    g_wth);
    cudaGetSymbolAddress((void**)&B.wtl,    g_wtl);
    cudaGetSymbolAddress((void**)&B.deg,    g_deg);
    cudaGetSymbolAddress((void**)&B.cur,    g_cur);
    cudaGetSymbolAddress((void**)&B.rowptr, g_rowptr);
    cudaGetSymbolAddress((void**)&B.esrc,   g_esrc);

    cudaFuncSetAttribute(hgemm_kernel<HEADS>, cudaFuncAttributeMaxDynamicSharedMemorySize, GEMM_SMEM);
    cudaFuncSetAttribute(hgemm_kernel<1>,     cudaFuncAttributeMaxDynamicSharedMemorySize, GEMM_SMEM);

    // ---- layer 1 front half first (keeps hgemm early for ncu window) ----
    {
        int na = NN * INC;
        split_kernel<<<(na + 255) / 256, 256>>>(x, B.ah, B.al, na);
    }
    run_gemm<HEADS>(INC, W1, a1_src, a1_dst, B);

    // ---- CSR build (needed before first aggregate) ----
    zero_int2_kernel<<<(NN + 255) / 256, 256>>>(B.deg, B.cur, NN);
    count_kernel<<<(ETOT + 255) / 256, 256>>>(ei, B.deg);
    scan_kernel<<<1, SCAN_T>>>(B.deg, B.rowptr);
    scatter_kernel<<<(ETOT + 255) / 256, 256>>>(ei, B.rowptr, B.cur, B.esrc);

    aggregate4_kernel<<<(NN * 32 + 255) / 256, 256>>>(
        B.rowptr, B.esrc, B.asrc, B.adst, B.hlin, b1, B.ah, B.al);

    run_gemm<HEADS>(FMAX, W2, a2_src, a2_dst, B);
    aggregate4_kernel<<<(NN * 32 + 255) / 256, 256>>>(
        B.rowptr, B.esrc, B.asrc, B.adst, B.hlin, b2, B.ah, B.al);

    run_gemm<1>(FMAX, W3, a3_src, a3_dst, B);
    aggregate1_kernel<<<(NN * 32 + 255) / 256, 256>>>(
        B.rowptr, B.esrc, B.asrc, B.adst, B.hlin, b3, (float*)d_out);
}

// round 15
// speedup vs baseline: 1.0389x; 1.0389x over previous
#include <cuda_runtime.h>
#include <cuda_bf16.h>
#include <cuda_fp16.h>
#include <math.h>
#include <stdint.h>

// Problem constants
#define NN     20000
#define EE     400000
#define ETOT   420000
#define INC    768
#define HID    128
#define HEADS  4
#define FMAX   512

// ---------------- device scratch ----------------
__device__ __half g_hlin[(size_t)NN * FMAX];
__device__ float g_asrc[(size_t)NN * HEADS];
__device__ float g_adst[(size_t)NN * HEADS];
__device__ __nv_bfloat16 g_ah [(size_t)NN * INC];
__device__ __nv_bfloat16 g_al [(size_t)NN * INC];
__device__ __nv_bfloat16 g_wth[(size_t)FMAX * INC];
__device__ __nv_bfloat16 g_wtl[(size_t)FMAX * INC];
__device__ int g_deg[NN];
__device__ int g_cur[NN];
__device__ int g_rowptr[NN + 1];
__device__ int g_esrc[ETOT];

// ---------------- misc helpers ----------------
__device__ __forceinline__ int clampN(int v) { return v < 0 ? 0 : (v >= NN ? NN - 1 : v); }
__device__ __forceinline__ uint32_t smem_u32(const void* p) {
    uint32_t a;
    asm("{ .reg .u64 t; cvta.to.shared.u64 t, %1; cvt.u32.u64 %0, t; }" : "=r"(a) : "l"(p));
    return a;
}

__global__ void zero_int2_kernel(int* __restrict__ a, int* __restrict__ b, int n) {
    int i = blockIdx.x * blockDim.x + threadIdx.x;
    if (i < n) { a[i] = 0; b[i] = 0; }
}

// ---------------- CSR build ----------------
__global__ void count_kernel(const int* __restrict__ ei, int* __restrict__ deg) {
    int e = blockIdx.x * blockDim.x + threadIdx.x;
    if (e >= ETOT) return;
    int d = (e < EE) ? clampN(ei[EE + e]) : e - EE;
    atomicAdd(&deg[d], 1);
}

#define SCAN_T 1024
#define SCAN_CH 20
__global__ void scan_kernel(const int* __restrict__ deg, int* __restrict__ rowptr) {
    __shared__ int sums[SCAN_T];
    int t = threadIdx.x;
    int base = t * SCAN_CH;
    int local = 0;
#pragma unroll
    for (int i = 0; i < SCAN_CH; i++) {
        int idx = base + i;
        if (idx < NN) local += deg[idx];
    }
    sums[t] = local;
    __syncthreads();
    for (int off = 1; off < SCAN_T; off <<= 1) {
        int v = (t >= off) ? sums[t - off] : 0;
        __syncthreads();
        sums[t] += v;
        __syncthreads();
    }
    int run = sums[t] - local;
#pragma unroll
    for (int i = 0; i < SCAN_CH; i++) {
        int idx = base + i;
        if (idx < NN) { rowptr[idx] = run; run += deg[idx]; }
    }
    if (t == SCAN_T - 1) rowptr[NN] = sums[SCAN_T - 1];
}

__global__ void scatter_kernel(const int* __restrict__ ei,
                               const int* __restrict__ rowptr,
                               int* __restrict__ cur, int* __restrict__ esrc) {
    int e = blockIdx.x * blockDim.x + threadIdx.x;
    if (e >= ETOT) return;
    int s, d;
    if (e < EE) { s = clampN(ei[e]); d = clampN(ei[EE + e]); } else { s = d = e - EE; }
    int pos = rowptr[d] + atomicAdd(&cur[d], 1);
    esrc[pos] = s;
}

// ---------------- fp32 -> bf16 hi/lo split (x only) ----------------
__global__ void split_kernel(const float* __restrict__ x,
                             __nv_bfloat16* __restrict__ hi,
                             __nv_bfloat16* __restrict__ lo, int n) {
    int i = blockIdx.x * blockDim.x + threadIdx.x;
    if (i >= n) return;
    float v = x[i];
    __nv_bfloat16 h = __float2bfloat16(v);
    hi[i] = h;
    lo[i] = __float2bfloat16(v - __bfloat162float(h));
}

// W [K,N] fp32 -> Wt hi/lo [N,K] bf16 via smem-tiled transpose
__global__ void splitT_kernel(const float* __restrict__ W,
                              __nv_bfloat16* __restrict__ hi,
                              __nv_bfloat16* __restrict__ lo, int K, int Nn) {
    __shared__ float t[32][33];
    const int tx = threadIdx.x;
    const int ty = threadIdx.y;
    const int n0 = blockIdx.x * 32;
    const int k0 = blockIdx.y * 32;
#pragma unroll
    for (int i = 0; i < 4; i++) {
        int k = k0 + ty + i * 8;
        t[ty + i * 8][tx] = W[(size_t)k * Nn + n0 + tx];
    }
    __syncthreads();
#pragma unroll
    for (int i = 0; i < 4; i++) {
        int n = n0 + ty + i * 8;
        float v = t[tx][ty + i * 8];
        __nv_bfloat16 h = __float2bfloat16(v);
        size_t o = (size_t)n * K + k0 + tx;
        hi[o] = h;
        lo[o] = __float2bfloat16(v - __bfloat162float(h));
    }
}

// ---------------- HMMA bf16 GEMM: BK=32, 2-stage cp.async (R13 core) --------
#define SPAD 40
#define TILE_ELEMS (128 * SPAD)
#define STAGE_ELEMS (4 * TILE_ELEMS)
#define GEMM_SMEM (2 * STAGE_ELEMS * 2)   // 81920 bytes

__device__ __forceinline__ void mma_bf16(float* c, const uint32_t* a, const uint32_t* b) {
    asm volatile("mma.sync.aligned.m16n8k16.row.col.f32.bf16.bf16.f32 "
                 "{%0,%1,%2,%3}, {%4,%5,%6,%7}, {%8,%9}, {%0,%1,%2,%3};"
                 : "+f"(c[0]), "+f"(c[1]), "+f"(c[2]), "+f"(c[3])
                 : "r"(a[0]), "r"(a[1]), "r"(a[2]), "r"(a[3]),
                   "r"(b[0]), "r"(b[1]));
}
#define LDM_X4(r0, r1, r2, r3, a) \
    asm volatile("ldmatrix.sync.aligned.m8n8.x4.shared.b16 {%0,%1,%2,%3}, [%4];" \
                 : "=r"(r0), "=r"(r1), "=r"(r2), "=r"(r3) : "r"(a))
#define CP_ASYNC16(dst, src) \
    asm volatile("cp.async.ca.shared.global [%0], [%1], 16;" :: "r"(dst), "l"(src))

template <int H>
__global__ void __launch_bounds__(256)
hgemm_kernel(const __nv_bfloat16* __restrict__ Ah,
             const __nv_bfloat16* __restrict__ Al,
             const __nv_bfloat16* __restrict__ Bh,
             const __nv_bfloat16* __restrict__ Bl,
             __half* __restrict__ C,
             const float* __restrict__ avec_src,
             const float* __restrict__ avec_dst,
             float* __restrict__ asrc,
             float* __restrict__ adst,
             int M, int K, int Nn) {
    extern __shared__ __nv_bfloat16 sm[];

    const int tid  = threadIdx.x;
    const int lane = tid & 31;
    const int wid  = tid >> 5;
    const int wm   = (wid >> 2) * 64;
    const int wn   = (wid & 3) * 32;
    const int row0 = blockIdx.y * 128;
    const int col0 = blockIdx.x * 128;
    const int g4   = lane >> 2;
    const int t4   = lane & 3;

    const int a_off = (lane & 15) * SPAD + (lane >> 4) * 8;
    const int b_off = ((lane & 7) + ((lane & 16) ? 8 : 0)) * SPAD + ((lane & 8) ? 8 : 0);

    const int lr = tid >> 1;
    const int lc = (tid & 1) * 16;

    float acc[4][4][4];
#pragma unroll
    for (int a = 0; a < 4; a++)
#pragma unroll
        for (int b = 0; b < 4; b++)
#pragma unroll
            for (int c = 0; c < 4; c++) acc[a][b][c] = 0.f;

    const int nCh = K >> 5;
    const int gra = min(row0 + lr, M - 1);
    const int grb = col0 + lr;
    const uint32_t smb = smem_u32(sm);

#define ISSUE(ch) do {                                                          \
    uint32_t sb_ = smb + (uint32_t)((ch) & 1) * (STAGE_ELEMS * 2);              \
    int kc0_ = (ch) << 5;                                                       \
    uint32_t d_ = sb_ + (uint32_t)(lr * SPAD + lc) * 2;                         \
    const __nv_bfloat16* pa_ = Ah + (size_t)gra * K + kc0_ + lc;                \
    const __nv_bfloat16* pb_ = Al + (size_t)gra * K + kc0_ + lc;                \
    const __nv_bfloat16* pc_ = Bh + (size_t)grb * K + kc0_ + lc;                \
    const __nv_bfloat16* pd_ = Bl + (size_t)grb * K + kc0_ + lc;                \
    CP_ASYNC16(d_ + 0 * TILE_ELEMS * 2,      pa_);                              \
    CP_ASYNC16(d_ + 0 * TILE_ELEMS * 2 + 16, pa_ + 8);                          \
    CP_ASYNC16(d_ + 1 * TILE_ELEMS * 2,      pb_);                              \
    CP_ASYNC16(d_ + 1 * TILE_ELEMS * 2 + 16, pb_ + 8);                          \
    CP_ASYNC16(d_ + 2 * TILE_ELEMS * 2,      pc_);                              \
    CP_ASYNC16(d_ + 2 * TILE_ELEMS * 2 + 16, pc_ + 8);                          \
    CP_ASYNC16(d_ + 3 * TILE_ELEMS * 2,      pd_);                              \
    CP_ASYNC16(d_ + 3 * TILE_ELEMS * 2 + 16, pd_ + 8);                          \
    asm volatile("cp.async.commit_group;");                                     \
} while (0)

    ISSUE(0);
    for (int ch = 0; ch < nCh; ch++) {
        if (ch + 1 < nCh) {
            ISSUE(ch + 1);
            asm volatile("cp.async.wait_group 1;");
        } else {
            asm volatile("cp.async.wait_group 0;");
        }
        __syncthreads();

        const uint32_t bAh = smb + (uint32_t)(ch & 1) * (STAGE_ELEMS * 2);
        const uint32_t bAl = bAh + TILE_ELEMS * 2;
        const uint32_t bBh = bAl + TILE_ELEMS * 2;
        const uint32_t bBl = bBh + TILE_ELEMS * 2;

#pragma unroll
        for (int ks = 0; ks < 32; ks += 16) {
            uint32_t bh[4][2], bl[4][2];
#pragma unroll
            for (int ntp = 0; ntp < 2; ntp++) {
                uint32_t off = (uint32_t)((wn + ntp * 16) * SPAD + ks + b_off) * 2;
                LDM_X4(bh[2 * ntp][0], bh[2 * ntp][1], bh[2 * ntp + 1][0], bh[2 * ntp + 1][1], bBh + off);
                LDM_X4(bl[2 * ntp][0], bl[2 * ntp][1], bl[2 * ntp + 1][0], bl[2 * ntp + 1][1], bBl + off);
            }
#pragma unroll
            for (int mt = 0; mt < 4; mt++) {
                uint32_t off = (uint32_t)((wm + mt * 16) * SPAD + ks + a_off) * 2;
                uint32_t ah[4], al[4];
                LDM_X4(ah[0], ah[1], ah[2], ah[3], bAh + off);
                LDM_X4(al[0], al[1], al[2], al[3], bAl + off);
#pragma unroll
                for (int nt = 0; nt < 4; nt++) {
                    mma_bf16(acc[mt][nt], ah, bh[nt]);
                    mma_bf16(acc[mt][nt], ah, bl[nt]);
                    mma_bf16(acc[mt][nt], al, bh[nt]);
                }
            }
        }
        __syncthreads();
    }
#undef ISSUE

    // ---- epilogue: store C (fp16) + attention dots via SMEM reduction ------
    // Each (row, head) pair is covered by exactly this CTA, so the reduction
    // never leaves the block: smem atomics + one plain STG. No global zeroing.
    const int h = col0 >> 7;
    float vs[4][2], vd[4][2];
#pragma unroll
    for (int nt = 0; nt < 4; nt++) {
        int gc = col0 + wn + nt * 8 + t4 * 2;
#pragma unroll
        for (int j = 0; j < 2; j++) {
            vs[nt][j] = avec_src[gc + j];
            vd[nt][j] = avec_dst[gc + j];
        }
    }

    float* s_red = (float*)sm;   // 256 floats: [0:128) src, [128:256) dst
    __syncthreads();             // all warps done reading tiles
    if (tid < 256) s_red[tid] = 0.f;
    __syncthreads();

#pragma unroll
    for (int mt = 0; mt < 4; mt++) {
        float ps0 = 0.f, pd0 = 0.f, ps1 = 0.f, pd1 = 0.f;
#pragma unroll
        for (int nt = 0; nt < 4; nt++) {
            int gm = row0 + wm + mt * 16 + g4;
            int gc = col0 + wn + nt * 8 + t4 * 2;
            if (gm < M)
                *(__half2*)&C[(size_t)gm * Nn + gc] =
                    __floats2half2_rn(acc[mt][nt][0], acc[mt][nt][1]);
            if (gm + 8 < M)
                *(__half2*)&C[(size_t)(gm + 8) * Nn + gc] =
                    __floats2half2_rn(acc[mt][nt][2], acc[mt][nt][3]);
            ps0 = fmaf(acc[mt][nt][0], vs[nt][0], fmaf(acc[mt][nt][1], vs[nt][1], ps0));
            pd0 = fmaf(acc[mt][nt][0], vd[nt][0], fmaf(acc[mt][nt][1], vd[nt][1], pd0));
            ps1 = fmaf(acc[mt][nt][2], vs[nt][0], fmaf(acc[mt][nt][3], vs[nt][1], ps1));
            pd1 = fmaf(acc[mt][nt][2], vd[nt][0], fmaf(acc[mt][nt][3], vd[nt][1], pd1));
        }
#pragma unroll
        for (int o = 1; o <= 2; o <<= 1) {
            ps0 += __shfl_xor_sync(0xffffffffu, ps0, o);
            pd0 += __shfl_xor_sync(0xffffffffu, pd0, o);
            ps1 += __shfl_xor_sync(0xffffffffu, ps1, o);
            pd1 += __shfl_xor_sync(0xffffffffu, pd1, o);
        }
        if (t4 == 0) {
            int r = wm + mt * 16 + g4;
            atomicAdd(&s_red[r],           ps0);
            atomicAdd(&s_red[128 + r],     pd0);
            atomicAdd(&s_red[r + 8],       ps1);
            atomicAdd(&s_red[128 + r + 8], pd1);
        }
    }
    __syncthreads();
    if (tid < 128) {
        int gm = row0 + tid;
        if (gm < M) {
            asrc[(size_t)gm * H + h] = s_red[tid];
            adst[(size_t)gm * H + h] = s_red[128 + tid];
        }
    }
}

// ---------------- fused aggregate, H=4: one warp per NODE (all heads) -------
__global__ void aggregate4_kernel(const int* __restrict__ rowptr,
                                  const int* __restrict__ esrc,
                                  const float* __restrict__ asrc,
                                  const float* __restrict__ adst,
                                  const __half* __restrict__ hlin,
                                  const float* __restrict__ bias,
                                  __nv_bfloat16* __restrict__ hi,
                                  __nv_bfloat16* __restrict__ lo) {
    int n = (blockIdx.x * blockDim.x + threadIdx.x) >> 5;
    int lane = threadIdx.x & 31;
    if (n >= NN) return;
    float4 ad = *(const float4*)&adst[(size_t)n * 4];
    int beg = rowptr[n], end = rowptr[n + 1];

    float4 acc0 = {0,0,0,0}, acc1 = {0,0,0,0}, acc2 = {0,0,0,0}, acc3 = {0,0,0,0};
    float4 ss = {0,0,0,0};

    for (int base = beg; base < end; base += 32) {
        int j = base + lane;
        float4 vj = {0,0,0,0};
        int sj = 0;
        if (j < end) {
            sj = esrc[j];
            float4 as = *(const float4*)&asrc[(size_t)sj * 4];
            float e0 = as.x + ad.x, e1 = as.y + ad.y, e2 = as.z + ad.z, e3 = as.w + ad.w;
            e0 = (e0 > 0.f) ? e0 : 0.2f * e0;
            e1 = (e1 > 0.f) ? e1 : 0.2f * e1;
            e2 = (e2 > 0.f) ? e2 : 0.2f * e2;
            e3 = (e3 > 0.f) ? e3 : 0.2f * e3;
            vj.x = __expf(e0); vj.y = __expf(e1); vj.z = __expf(e2); vj.w = __expf(e3);
        }
        int cnt = min(32, end - base);
        for (int t = 0; t < cnt; t++) {
            int s   = __shfl_sync(0xffffffffu, sj, t);
            float w0 = __shfl_sync(0xffffffffu, vj.x, t);
            float w1 = __shfl_sync(0xffffffffu, vj.y, t);
            float w2 = __shfl_sync(0xffffffffu, vj.z, t);
            float w3 = __shfl_sync(0xffffffffu, vj.w, t);
            const uint2* p = (const uint2*)(hlin + (size_t)s * FMAX);
            uint2 u0 = p[lane];
            uint2 u1 = p[lane + 32];
            uint2 u2 = p[lane + 64];
            uint2 u3 = p[lane + 96];
            float2 a0 = __half22float2(*(const __half2*)&u0.x);
            float2 b0 = __half22float2(*(const __half2*)&u0.y);
            float2 a1 = __half22float2(*(const __half2*)&u1.x);
            float2 b1 = __half22float2(*(const __half2*)&u1.y);
            float2 a2 = __half22float2(*(const __half2*)&u2.x);
            float2 b2 = __half22float2(*(const __half2*)&u2.y);
            float2 a3 = __half22float2(*(const __half2*)&u3.x);
            float2 b3 = __half22float2(*(const __half2*)&u3.y);
            acc0.x = fmaf(w0, a0.x, acc0.x); acc0.y = fmaf(w0, a0.y, acc0.y);
            acc0.z = fmaf(w0, b0.x, acc0.z); acc0.w = fmaf(w0, b0.y, acc0.w);
            acc1.x = fmaf(w1, a1.x, acc1.x); acc1.y = fmaf(w1, a1.y, acc1.y);
            acc1.z = fmaf(w1, b1.x, acc1.z); acc1.w = fmaf(w1, b1.y, acc1.w);
            acc2.x = fmaf(w2, a2.x, acc2.x); acc2.y = fmaf(w2, a2.y, acc2.y);
            acc2.z = fmaf(w2, b2.x, acc2.z); acc2.w = fmaf(w2, b2.y, acc2.w);
            acc3.x = fmaf(w3, a3.x, acc3.x); acc3.y = fmaf(w3, a3.y, acc3.y);
            acc3.z = fmaf(w3, b3.x, acc3.z); acc3.w = fmaf(w3, b3.y, acc3.w);
            ss.x += w0; ss.y += w1; ss.z += w2; ss.w += w3;
        }
    }

#define FIN(acch, sh, hh) do {                                                  \
    float inv = 1.f / ((sh) + 1e-16f);                                          \
    float4 bv = *(const float4*)&bias[(hh) * HID + lane * 4];                   \
    float4 o;                                                                   \
    o.x = (acch).x * inv + bv.x;                                                \
    o.y = (acch).y * inv + bv.y;                                                \
    o.z = (acch).z * inv + bv.z;                                                \
    o.w = (acch).w * inv + bv.w;                                                \
    o.x = (o.x > 0.f) ? o.x : expm1f(o.x);                                      \
    o.y = (o.y > 0.f) ? o.y : expm1f(o.y);                                      \
    o.z = (o.z > 0.f) ? o.z : expm1f(o.z);                                      \
    o.w = (o.w > 0.f) ? o.w : expm1f(o.w);                                      \
    size_t off = ((size_t)n * 4 + (hh)) * HID + lane * 4;                       \
    __nv_bfloat16 hx = __float2bfloat16(o.x);                                   \
    __nv_bfloat16 hy = __float2bfloat16(o.y);                                   \
    __nv_bfloat16 hz = __float2bfloat16(o.z);                                   \
    __nv_bfloat16 hw = __float2bfloat16(o.w);                                   \
    hi[off + 0] = hx;  lo[off + 0] = __float2bfloat16(o.x - __bfloat162float(hx)); \
    hi[off + 1] = hy;  lo[off + 1] = __float2bfloat16(o.y - __bfloat162float(hy)); \
    hi[off + 2] = hz;  lo[off + 2] = __float2bfloat16(o.z - __bfloat162float(hz)); \
    hi[off + 3] = hw;  lo[off + 3] = __float2bfloat16(o.w - __bfloat162float(hw)); \
} while (0)

    FIN(acc0, ss.x, 0);
    FIN(acc1, ss.y, 1);
    FIN(acc2, ss.z, 2);
    FIN(acc3, ss.w, 3);
#undef FIN
}

// ---------------- fused aggregate H=1 (layer 3, fp32 out) -------------------
__global__ void aggregate1_kernel(const int* __restrict__ rowptr,
                                  const int* __restrict__ esrc,
                                  const float* __restrict__ asrc,
                                  const float* __restrict__ adst,
                                  const __half* __restrict__ hlin,
                                  const float* __restrict__ bias,
                                  float* __restrict__ out) {
    int n = (blockIdx.x * blockDim.x + threadIdx.x) >> 5;
    int lane = threadIdx.x & 31;
    if (n >= NN) return;
    float adn = adst[n];
    int beg = rowptr[n], end = rowptr[n + 1];

    float4 acc = {0,0,0,0};
    float ssum = 0.f;

    for (int base = beg; base < end; base += 32) {
        int j = base + lane;
        float vj = 0.f;
        int sj = 0;
        if (j < end) {
            sj = esrc[j];
            float v = asrc[sj] + adn;
            v = (v > 0.f) ? v : 0.2f * v;
            vj = __expf(v);
        }
        int cnt = min(32, end - base);
        for (int t = 0; t < cnt; t++) {
            float v = __shfl_sync(0xffffffffu, vj, t);
            int s   = __shfl_sync(0xffffffffu, sj, t);
            const uint2* hp = (const uint2*)(hlin + (size_t)s * HID);
            uint2 u = hp[lane];
            float2 f0 = __half22float2(*(const __half2*)&u.x);
            float2 f1 = __half22float2(*(const __half2*)&u.y);
            acc.x = fmaf(v, f0.x, acc.x);
            acc.y = fmaf(v, f0.y, acc.y);
            acc.z = fmaf(v, f1.x, acc.z);
            acc.w = fmaf(v, f1.y, acc.w);
            ssum += v;
        }
    }
    float inv = 1.f / (ssum + 1e-16f);
    float4 bv = *(const float4*)&bias[lane * 4];
    float4 o;
    o.x = acc.x * inv + bv.x;
    o.y = acc.y * inv + bv.y;
    o.z = acc.z * inv + bv.z;
    o.w = acc.w * inv + bv.w;
    *(float4*)&out[(size_t)n * HID + lane * 4] = o;
}

// ---------------- host orchestration ----------------
struct Buffers {
    __half* hlin;
    float *asrc, *adst;
    __nv_bfloat16 *ah, *al, *wth, *wtl;
    int *deg, *cur, *rowptr, *esrc;
};

template <int H>
static void run_gemm(int K, const float* W, const float* a_src, const float* a_dst,
                     const Buffers& B) {
    const int F = H * HID;
    dim3 tgrid(F / 32, K / 32);
    splitT_kernel<<<tgrid, dim3(32, 8)>>>(W, B.wth, B.wtl, K, F);
    dim3 grid(F / 128, (NN + 127) / 128);
    hgemm_kernel<H><<<grid, 256, GEMM_SMEM>>>(B.ah, B.al, B.wth, B.wtl, B.hlin,
                                              a_src, a_dst, B.asrc, B.adst, NN, K, F);
}

extern "C" void kernel_launch(void* const* d_in, const int* in_sizes, int n_in,
                              void* d_out, int out_size) {
    const float* x       = (const float*)d_in[0];
    const int*   ei      = (const int*)d_in[1];
    const float* W1      = (const float*)d_in[2];
    const float* a1_src  = (const float*)d_in[3];
    const float* a1_dst  = (const float*)d_in[4];
    const float* b1      = (const float*)d_in[5];
    const float* W2      = (const float*)d_in[6];
    const float* a2_src  = (const float*)d_in[7];
    const float* a2_dst  = (const float*)d_in[8];
    const float* b2      = (const float*)d_in[9];
    const float* W3      = (const float*)d_in[10];
    const float* a3_src  = (const float*)d_in[11];
    const float* a3_dst  = (const float*)d_in[12];
    const float* b3      = (const float*)d_in[13];

    Buffers B;
    cudaGetSymbolAddress((void**)&B.hlin,   g_hlin);
    cudaGetSymbolAddress((void**)&B.asrc,   g_asrc);
    cudaGetSymbolAddress((void**)&B.adst,   g_adst);
    cudaGetSymbolAddress((void**)&B.ah,     g_ah);
    cudaGetSymbolAddress((void**)&B.al,     g_al);
    cudaGetSymbolAddress((void**)&B.wth,    g_wth);
    cudaGetSymbolAddress((void**)&B.wtl,    g_wtl);
    cudaGetSymbolAddress((void**)&B.deg,    g_deg);
    cudaGetSymbolAddress((void**)&B.cur,    g_cur);
    cudaGetSymbolAddress((void**)&B.rowptr, g_rowptr);
    cudaGetSymbolAddress((void**)&B.esrc,   g_esrc);

    cudaFuncSetAttribute(hgemm_kernel<HEADS>, cudaFuncAttributeMaxDynamicSharedMemorySize, GEMM_SMEM);
    cudaFuncSetAttribute(hgemm_kernel<1>,     cudaFuncAttributeMaxDynamicSharedMemorySize, GEMM_SMEM);

    // ---- layer 1 front half first (keeps hgemm early for ncu window) ----
    {
        int na = NN * INC;
        split_kernel<<<(na + 255) / 256, 256>>>(x, B.ah, B.al, na);
    }
    run_gemm<HEADS>(INC, W1, a1_src, a1_dst, B);

    // ---- CSR build (needed before first aggregate) ----
    zero_int2_kernel<<<(NN + 255) / 256, 256>>>(B.deg, B.cur, NN);
    count_kernel<<<(ETOT + 255) / 256, 256>>>(ei, B.deg);
    scan_kernel<<<1, SCAN_T>>>(B.deg, B.rowptr);
    scatter_kernel<<<(ETOT + 255) / 256, 256>>>(ei, B.rowptr, B.cur, B.esrc);

    aggregate4_kernel<<<(NN * 32 + 255) / 256, 256>>>(
        B.rowptr, B.esrc, B.asrc, B.adst, B.hlin, b1, B.ah, B.al);

    run_gemm<HEADS>(FMAX, W2, a2_src, a2_dst, B);
    aggregate4_kernel<<<(NN * 32 + 255) / 256, 256>>>(
        B.rowptr, B.esrc, B.asrc, B.adst, B.hlin, b2, B.ah, B.al);

    run_gemm<1>(FMAX, W3, a3_src, a3_dst, B);
    aggregate1_kernel<<<(NN * 32 + 255) / 256, 256>>>(
        B.rowptr, B.esrc, B.asrc, B.adst, B.hlin, b3, (float*)d_out);
}

// round 16
// speedup vs baseline: 1.2162x; 1.1707x over previous
#include <cuda_runtime.h>
#include <cuda_bf16.h>
#include <cuda_fp16.h>
#include <math.h>
#include <stdint.h>

// Problem constants
#define NN     20000
#define EE     400000
#define ETOT   420000
#define INC    768
#define HID    128
#define HEADS  4
#define FMAX   512

// ---------------- device scratch ----------------
__device__ __half g_hlin[(size_t)NN * FMAX];
__device__ float g_asrc[(size_t)NN * HEADS];
__device__ float g_adst[(size_t)NN * HEADS];
__device__ __half g_ah [(size_t)NN * INC];     // A hi (fp16)
__device__ __half g_al [(size_t)NN * INC];     // A lo (fp16)
__device__ __half g_wth[(size_t)FMAX * INC];   // W^T (fp16, single)
__device__ int g_deg[NN];
__device__ int g_cur[NN];
__device__ int g_rowptr[NN + 1];
__device__ int g_esrc[ETOT];

// ---------------- misc helpers ----------------
__device__ __forceinline__ int clampN(int v) { return v < 0 ? 0 : (v >= NN ? NN - 1 : v); }
__device__ __forceinline__ uint32_t smem_u32(const void* p) {
    uint32_t a;
    asm("{ .reg .u64 t; cvta.to.shared.u64 t, %1; cvt.u32.u64 %0, t; }" : "=r"(a) : "l"(p));
    return a;
}

__global__ void zero_int2_kernel(int* __restrict__ a, int* __restrict__ b, int n) {
    int i = blockIdx.x * blockDim.x + threadIdx.x;
    if (i < n) { a[i] = 0; b[i] = 0; }
}

// ---------------- CSR build ----------------
__global__ void count_kernel(const int* __restrict__ ei, int* __restrict__ deg) {
    int e = blockIdx.x * blockDim.x + threadIdx.x;
    if (e >= ETOT) return;
    int d = (e < EE) ? clampN(ei[EE + e]) : e - EE;
    atomicAdd(&deg[d], 1);
}

#define SCAN_T 1024
#define SCAN_CH 20
__global__ void scan_kernel(const int* __restrict__ deg, int* __restrict__ rowptr) {
    __shared__ int sums[SCAN_T];
    int t = threadIdx.x;
    int base = t * SCAN_CH;
    int local = 0;
#pragma unroll
    for (int i = 0; i < SCAN_CH; i++) {
        int idx = base + i;
        if (idx < NN) local += deg[idx];
    }
    sums[t] = local;
    __syncthreads();
    for (int off = 1; off < SCAN_T; off <<= 1) {
        int v = (t >= off) ? sums[t - off] : 0;
        __syncthreads();
        sums[t] += v;
        __syncthreads();
    }
    int run = sums[t] - local;
#pragma unroll
    for (int i = 0; i < SCAN_CH; i++) {
        int idx = base + i;
        if (idx < NN) { rowptr[idx] = run; run += deg[idx]; }
    }
    if (t == SCAN_T - 1) rowptr[NN] = sums[SCAN_T - 1];
}

__global__ void scatter_kernel(const int* __restrict__ ei,
                               const int* __restrict__ rowptr,
                               int* __restrict__ cur, int* __restrict__ esrc) {
    int e = blockIdx.x * blockDim.x + threadIdx.x;
    if (e >= ETOT) return;
    int s, d;
    if (e < EE) { s = clampN(ei[e]); d = clampN(ei[EE + e]); } else { s = d = e - EE; }
    int pos = rowptr[d] + atomicAdd(&cur[d], 1);
    esrc[pos] = s;
}

// ---------------- fp32 -> fp16 hi/lo split (x only) ----------------
__global__ void split_kernel(const float* __restrict__ x,
                             __half* __restrict__ hi,
                             __half* __restrict__ lo, int n) {
    int i = blockIdx.x * blockDim.x + threadIdx.x;
    if (i >= n) return;
    float v = x[i];
    __half h = __float2half_rn(v);
    hi[i] = h;
    lo[i] = __float2half_rn(v - __half2float(h));
}

// W [K,N] fp32 -> Wt [N,K] fp16 via smem-tiled transpose (single precision tile)
__global__ void splitT_kernel(const float* __restrict__ W,
                              __half* __restrict__ hi, int K, int Nn) {
    __shared__ float t[32][33];
    const int tx = threadIdx.x;
    const int ty = threadIdx.y;
    const int n0 = blockIdx.x * 32;
    const int k0 = blockIdx.y * 32;
#pragma unroll
    for (int i = 0; i < 4; i++) {
        int k = k0 + ty + i * 8;
        t[ty + i * 8][tx] = W[(size_t)k * Nn + n0 + tx];
    }
    __syncthreads();
#pragma unroll
    for (int i = 0; i < 4; i++) {
        int n = n0 + ty + i * 8;
        hi[(size_t)n * K + k0 + tx] = __float2half_rn(t[tx][ty + i * 8]);
    }
}

// ---------------- HMMA fp16 GEMM: 2-product split (Ah+Al)*Bh ----------------
// BK=32, 2-stage cp.async, 3 tiles per stage (Ah, Al, Bh). SPAD=40 conflict-free.
#define SPAD 40
#define TILE_ELEMS (128 * SPAD)
#define STAGE_ELEMS (3 * TILE_ELEMS)
#define GEMM_SMEM (2 * STAGE_ELEMS * 2)   // 61440 bytes

__device__ __forceinline__ void mma_f16(float* c, const uint32_t* a, const uint32_t* b) {
    asm volatile("mma.sync.aligned.m16n8k16.row.col.f32.f16.f16.f32 "
                 "{%0,%1,%2,%3}, {%4,%5,%6,%7}, {%8,%9}, {%0,%1,%2,%3};"
                 : "+f"(c[0]), "+f"(c[1]), "+f"(c[2]), "+f"(c[3])
                 : "r"(a[0]), "r"(a[1]), "r"(a[2]), "r"(a[3]),
                   "r"(b[0]), "r"(b[1]));
}
#define LDM_X4(r0, r1, r2, r3, a) \
    asm volatile("ldmatrix.sync.aligned.m8n8.x4.shared.b16 {%0,%1,%2,%3}, [%4];" \
                 : "=r"(r0), "=r"(r1), "=r"(r2), "=r"(r3) : "r"(a))
#define CP_ASYNC16(dst, src) \
    asm volatile("cp.async.ca.shared.global [%0], [%1], 16;" :: "r"(dst), "l"(src))

template <int H>
__global__ void __launch_bounds__(256)
hgemm_kernel(const __half* __restrict__ Ah,
             const __half* __restrict__ Al,
             const __half* __restrict__ Bh,
             __half* __restrict__ C,
             const float* __restrict__ avec_src,
             const float* __restrict__ avec_dst,
             float* __restrict__ asrc,
             float* __restrict__ adst,
             int M, int K, int Nn) {
    extern __shared__ __half sm[];

    const int tid  = threadIdx.x;
    const int lane = tid & 31;
    const int wid  = tid >> 5;
    const int wm   = (wid >> 2) * 64;
    const int wn   = (wid & 3) * 32;
    const int row0 = blockIdx.y * 128;
    const int col0 = blockIdx.x * 128;
    const int g4   = lane >> 2;
    const int t4   = lane & 3;

    const int a_off = (lane & 15) * SPAD + (lane >> 4) * 8;
    const int b_off = ((lane & 7) + ((lane & 16) ? 8 : 0)) * SPAD + ((lane & 8) ? 8 : 0);

    const int lr = tid >> 1;
    const int lc = (tid & 1) * 16;

    float acc[4][4][4];
#pragma unroll
    for (int a = 0; a < 4; a++)
#pragma unroll
        for (int b = 0; b < 4; b++)
#pragma unroll
            for (int c = 0; c < 4; c++) acc[a][b][c] = 0.f;

    const int nCh = K >> 5;
    const int gra = min(row0 + lr, M - 1);
    const int grb = col0 + lr;
    const uint32_t smb = smem_u32(sm);

#define ISSUE(ch) do {                                                          \
    uint32_t sb_ = smb + (uint32_t)((ch) & 1) * (STAGE_ELEMS * 2);              \
    int kc0_ = (ch) << 5;                                                       \
    uint32_t d_ = sb_ + (uint32_t)(lr * SPAD + lc) * 2;                         \
    const __half* pa_ = Ah + (size_t)gra * K + kc0_ + lc;                       \
    const __half* pb_ = Al + (size_t)gra * K + kc0_ + lc;                       \
    const __half* pc_ = Bh + (size_t)grb * K + kc0_ + lc;                       \
    CP_ASYNC16(d_ + 0 * TILE_ELEMS * 2,      pa_);                              \
    CP_ASYNC16(d_ + 0 * TILE_ELEMS * 2 + 16, pa_ + 8);                          \
    CP_ASYNC16(d_ + 1 * TILE_ELEMS * 2,      pb_);                              \
    CP_ASYNC16(d_ + 1 * TILE_ELEMS * 2 + 16, pb_ + 8);                          \
    CP_ASYNC16(d_ + 2 * TILE_ELEMS * 2,      pc_);                              \
    CP_ASYNC16(d_ + 2 * TILE_ELEMS * 2 + 16, pc_ + 8);                          \
    asm volatile("cp.async.commit_group;");                                     \
} while (0)

    ISSUE(0);
    for (int ch = 0; ch < nCh; ch++) {
        if (ch + 1 < nCh) {
            ISSUE(ch + 1);
            asm volatile("cp.async.wait_group 1;");
        } else {
            asm volatile("cp.async.wait_group 0;");
        }
        __syncthreads();

        const uint32_t bAh = smb + (uint32_t)(ch & 1) * (STAGE_ELEMS * 2);
        const uint32_t bAl = bAh + TILE_ELEMS * 2;
        const uint32_t bBh = bAl + TILE_ELEMS * 2;

#pragma unroll
        for (int ks = 0; ks < 32; ks += 16) {
            uint32_t bh[4][2];
#pragma unroll
            for (int ntp = 0; ntp < 2; ntp++) {
                uint32_t off = (uint32_t)((wn + ntp * 16) * SPAD + ks + b_off) * 2;
                LDM_X4(bh[2 * ntp][0], bh[2 * ntp][1], bh[2 * ntp + 1][0], bh[2 * ntp + 1][1], bBh + off);
            }
#pragma unroll
            for (int mt = 0; mt < 4; mt++) {
                uint32_t off = (uint32_t)((wm + mt * 16) * SPAD + ks + a_off) * 2;
                uint32_t ah[4], al[4];
                LDM_X4(ah[0], ah[1], ah[2], ah[3], bAh + off);
                LDM_X4(al[0], al[1], al[2], al[3], bAl + off);
#pragma unroll
                for (int nt = 0; nt < 4; nt++) {
                    mma_f16(acc[mt][nt], ah, bh[nt]);
                    mma_f16(acc[mt][nt], al, bh[nt]);
                }
            }
        }
        __syncthreads();
    }
#undef ISSUE

    // ---- epilogue: store C (fp16) + attention dots via SMEM reduction ------
    const int h = col0 >> 7;
    float vs[4][2], vd[4][2];
#pragma unroll
    for (int nt = 0; nt < 4; nt++) {
        int gc = col0 + wn + nt * 8 + t4 * 2;
#pragma unroll
        for (int j = 0; j < 2; j++) {
            vs[nt][j] = avec_src[gc + j];
            vd[nt][j] = avec_dst[gc + j];
        }
    }

    float* s_red = (float*)sm;   // 256 floats
    __syncthreads();
    if (tid < 256) s_red[tid] = 0.f;
    __syncthreads();

#pragma unroll
    for (int mt = 0; mt < 4; mt++) {
        float ps0 = 0.f, pd0 = 0.f, ps1 = 0.f, pd1 = 0.f;
#pragma unroll
        for (int nt = 0; nt < 4; nt++) {
            int gm = row0 + wm + mt * 16 + g4;
            int gc = col0 + wn + nt * 8 + t4 * 2;
            if (gm < M)
                *(__half2*)&C[(size_t)gm * Nn + gc] =
                    __floats2half2_rn(acc[mt][nt][0], acc[mt][nt][1]);
            if (gm + 8 < M)
                *(__half2*)&C[(size_t)(gm + 8) * Nn + gc] =
                    __floats2half2_rn(acc[mt][nt][2], acc[mt][nt][3]);
            ps0 = fmaf(acc[mt][nt][0], vs[nt][0], fmaf(acc[mt][nt][1], vs[nt][1], ps0));
            pd0 = fmaf(acc[mt][nt][0], vd[nt][0], fmaf(acc[mt][nt][1], vd[nt][1], pd0));
            ps1 = fmaf(acc[mt][nt][2], vs[nt][0], fmaf(acc[mt][nt][3], vs[nt][1], ps1));
            pd1 = fmaf(acc[mt][nt][2], vd[nt][0], fmaf(acc[mt][nt][3], vd[nt][1], pd1));
        }
#pragma unroll
        for (int o = 1; o <= 2; o <<= 1) {
            ps0 += __shfl_xor_sync(0xffffffffu, ps0, o);
            pd0 += __shfl_xor_sync(0xffffffffu, pd0, o);
            ps1 += __shfl_xor_sync(0xffffffffu, ps1, o);
            pd1 += __shfl_xor_sync(0xffffffffu, pd1, o);
        }
        if (t4 == 0) {
            int r = wm + mt * 16 + g4;
            atomicAdd(&s_red[r],           ps0);
            atomicAdd(&s_red[128 + r],     pd0);
            atomicAdd(&s_red[r + 8],       ps1);
            atomicAdd(&s_red[128 + r + 8], pd1);
        }
    }
    __syncthreads();
    if (tid < 128) {
        int gm = row0 + tid;
        if (gm < M) {
            asrc[(size_t)gm * H + h] = s_red[tid];
            adst[(size_t)gm * H + h] = s_red[128 + tid];
        }
    }
}

// ---------------- fused aggregate, H=4: one warp per NODE (all heads) -------
__global__ void aggregate4_kernel(const int* __restrict__ rowptr,
                                  const int* __restrict__ esrc,
                                  const float* __restrict__ asrc,
                                  const float* __restrict__ adst,
                                  const __half* __restrict__ hlin,
                                  const float* __restrict__ bias,
                                  __half* __restrict__ hi,
                                  __half* __restrict__ lo) {
    int n = (blockIdx.x * blockDim.x + threadIdx.x) >> 5;
    int lane = threadIdx.x & 31;
    if (n >= NN) return;
    float4 ad = *(const float4*)&adst[(size_t)n * 4];
    int beg = rowptr[n], end = rowptr[n + 1];

    float4 acc0 = {0,0,0,0}, acc1 = {0,0,0,0}, acc2 = {0,0,0,0}, acc3 = {0,0,0,0};
    float4 ss = {0,0,0,0};

    for (int base = beg; base < end; base += 32) {
        int j = base + lane;
        float4 vj = {0,0,0,0};
        int sj = 0;
        if (j < end) {
            sj = esrc[j];
            float4 as = *(const float4*)&asrc[(size_t)sj * 4];
            float e0 = as.x + ad.x, e1 = as.y + ad.y, e2 = as.z + ad.z, e3 = as.w + ad.w;
            e0 = (e0 > 0.f) ? e0 : 0.2f * e0;
            e1 = (e1 > 0.f) ? e1 : 0.2f * e1;
            e2 = (e2 > 0.f) ? e2 : 0.2f * e2;
            e3 = (e3 > 0.f) ? e3 : 0.2f * e3;
            vj.x = __expf(e0); vj.y = __expf(e1); vj.z = __expf(e2); vj.w = __expf(e3);
        }
        int cnt = min(32, end - base);
        for (int t = 0; t < cnt; t++) {
            int s   = __shfl_sync(0xffffffffu, sj, t);
            float w0 = __shfl_sync(0xffffffffu, vj.x, t);
            float w1 = __shfl_sync(0xffffffffu, vj.y, t);
            float w2 = __shfl_sync(0xffffffffu, vj.z, t);
            float w3 = __shfl_sync(0xffffffffu, vj.w, t);
            const uint2* p = (const uint2*)(hlin + (size_t)s * FMAX);
            uint2 u0 = p[lane];
            uint2 u1 = p[lane + 32];
            uint2 u2 = p[lane + 64];
            uint2 u3 = p[lane + 96];
            float2 a0 = __half22float2(*(const __half2*)&u0.x);
            float2 b0 = __half22float2(*(const __half2*)&u0.y);
            float2 a1 = __half22float2(*(const __half2*)&u1.x);
            float2 b1 = __half22float2(*(const __half2*)&u1.y);
            float2 a2 = __half22float2(*(const __half2*)&u2.x);
            float2 b2 = __half22float2(*(const __half2*)&u2.y);
            float2 a3 = __half22float2(*(const __half2*)&u3.x);
            float2 b3 = __half22float2(*(const __half2*)&u3.y);
            acc0.x = fmaf(w0, a0.x, acc0.x); acc0.y = fmaf(w0, a0.y, acc0.y);
            acc0.z = fmaf(w0, b0.x, acc0.z); acc0.w = fmaf(w0, b0.y, acc0.w);
            acc1.x = fmaf(w1, a1.x, acc1.x); acc1.y = fmaf(w1, a1.y, acc1.y);
            acc1.z = fmaf(w1, b1.x, acc1.z); acc1.w = fmaf(w1, b1.y, acc1.w);
            acc2.x = fmaf(w2, a2.x, acc2.x); acc2.y = fmaf(w2, a2.y, acc2.y);
            acc2.z = fmaf(w2, b2.x, acc2.z); acc2.w = fmaf(w2, b2.y, acc2.w);
            acc3.x = fmaf(w3, a3.x, acc3.x); acc3.y = fmaf(w3, a3.y, acc3.y);
            acc3.z = fmaf(w3, b3.x, acc3.z); acc3.w = fmaf(w3, b3.y, acc3.w);
            ss.x += w0; ss.y += w1; ss.z += w2; ss.w += w3;
        }
    }

#define FIN(acch, sh, hh) do {                                                  \
    float inv = 1.f / ((sh) + 1e-16f);                                          \
    float4 bv = *(const float4*)&bias[(hh) * HID + lane * 4];                   \
    float4 o;                                                                   \
    o.x = (acch).x * inv + bv.x;                                                \
    o.y = (acch).y * inv + bv.y;                                                \
    o.z = (acch).z * inv + bv.z;                                                \
    o.w = (acch).w * inv + bv.w;                                                \
    o.x = (o.x > 0.f) ? o.x : expm1f(o.x);                                      \
    o.y = (o.y > 0.f) ? o.y : expm1f(o.y);                                      \
    o.z = (o.z > 0.f) ? o.z : expm1f(o.z);                                      \
    o.w = (o.w > 0.f) ? o.w : expm1f(o.w);                                      \
    size_t off = ((size_t)n * 4 + (hh)) * HID + lane * 4;                       \
    __half hx = __float2half_rn(o.x);                                           \
    __half hy = __float2half_rn(o.y);                                           \
    __half hz = __float2half_rn(o.z);                                           \
    __half hw = __float2half_rn(o.w);                                           \
    hi[off + 0] = hx;  lo[off + 0] = __float2half_rn(o.x - __half2float(hx));   \
    hi[off + 1] = hy;  lo[off + 1] = __float2half_rn(o.y - __half2float(hy));   \
    hi[off + 2] = hz;  lo[off + 2] = __float2half_rn(o.z - __half2float(hz));   \
    hi[off + 3] = hw;  lo[off + 3] = __float2half_rn(o.w - __half2float(hw));   \
} while (0)

    FIN(acc0, ss.x, 0);
    FIN(acc1, ss.y, 1);
    FIN(acc2, ss.z, 2);
    FIN(acc3, ss.w, 3);
#undef FIN
}

// ---------------- fused aggregate H=1 (layer 3, fp32 out) -------------------
__global__ void aggregate1_kernel(const int* __restrict__ rowptr,
                                  const int* __restrict__ esrc,
                                  const float* __restrict__ asrc,
                                  const float* __restrict__ adst,
                                  const __half* __restrict__ hlin,
                                  const float* __restrict__ bias,
                                  float* __restrict__ out) {
    int n = (blockIdx.x * blockDim.x + threadIdx.x) >> 5;
    int lane = threadIdx.x & 31;
    if (n >= NN) return;
    float adn = adst[n];
    int beg = rowptr[n], end = rowptr[n + 1];

    float4 acc = {0,0,0,0};
    float ssum = 0.f;

    for (int base = beg; base < end; base += 32) {
        int j = base + lane;
        float vj = 0.f;
        int sj = 0;
        if (j < end) {
            sj = esrc[j];
            float v = asrc[sj] + adn;
            v = (v > 0.f) ? v : 0.2f * v;
            vj = __expf(v);
        }
        int cnt = min(32, end - base);
        for (int t = 0; t < cnt; t++) {
            float v = __shfl_sync(0xffffffffu, vj, t);
            int s   = __shfl_sync(0xffffffffu, sj, t);
            const uint2* hp = (const uint2*)(hlin + (size_t)s * HID);
            uint2 u = hp[lane];
            float2 f0 = __half22float2(*(const __half2*)&u.x);
            float2 f1 = __half22float2(*(const __half2*)&u.y);
            acc.x = fmaf(v, f0.x, acc.x);
            acc.y = fmaf(v, f0.y, acc.y);
            acc.z = fmaf(v, f1.x, acc.z);
            acc.w = fmaf(v, f1.y, acc.w);
            ssum += v;
        }
    }
    float inv = 1.f / (ssum + 1e-16f);
    float4 bv = *(const float4*)&bias[lane * 4];
    float4 o;
    o.x = acc.x * inv + bv.x;
    o.y = acc.y * inv + bv.y;
    o.z = acc.z * inv + bv.z;
    o.w = acc.w * inv + bv.w;
    *(float4*)&out[(size_t)n * HID + lane * 4] = o;
}

// ---------------- host orchestration ----------------
struct Buffers {
    __half* hlin;
    float *asrc, *adst;
    __half *ah, *al, *wth;
    int *deg, *cur, *rowptr, *esrc;
};

template <int H>
static void run_gemm(int K, const float* W, const float* a_src, const float* a_dst,
                     const Buffers& B) {
    const int F = H * HID;
    dim3 tgrid(F / 32, K / 32);
    splitT_kernel<<<tgrid, dim3(32, 8)>>>(W, B.wth, K, F);
    dim3 grid(F / 128, (NN + 127) / 128);
    hgemm_kernel<H><<<grid, 256, GEMM_SMEM>>>(B.ah, B.al, B.wth, B.hlin,
                                              a_src, a_dst, B.asrc, B.adst, NN, K, F);
}

extern "C" void kernel_launch(void* const* d_in, const int* in_sizes, int n_in,
                              void* d_out, int out_size) {
    const float* x       = (const float*)d_in[0];
    const int*   ei      = (const int*)d_in[1];
    const float* W1      = (const float*)d_in[2];
    const float* a1_src  = (const float*)d_in[3];
    const float* a1_dst  = (const float*)d_in[4];
    const float* b1      = (const float*)d_in[5];
    const float* W2      = (const float*)d_in[6];
    const float* a2_src  = (const float*)d_in[7];
    const float* a2_dst  = (const float*)d_in[8];
    const float* b2      = (const float*)d_in[9];
    const float* W3      = (const float*)d_in[10];
    const float* a3_src  = (const float*)d_in[11];
    const float* a3_dst  = (const float*)d_in[12];
    const float* b3      = (const float*)d_in[13];

    Buffers B;
    cudaGetSymbolAddress((void**)&B.hlin,   g_hlin);
    cudaGetSymbolAddress((void**)&B.asrc,   g_asrc);
    cudaGetSymbolAddress((void**)&B.adst,   g_adst);
    cudaGetSymbolAddress((void**)&B.ah,     g_ah);
    cudaGetSymbolAddress((void**)&B.al,     g_al);
    cudaGetSymbolAddress((void**)&B.wth,    g_wth);
    cudaGetSymbolAddress((void**)&B.deg,    g_deg);
    cudaGetSymbolAddress((void**)&B.cur,    g_cur);
    cudaGetSymbolAddress((void**)&B.rowptr, g_rowptr);
    cudaGetSymbolAddress((void**)&B.esrc,   g_esrc);

    cudaFuncSetAttribute(hgemm_kernel<HEADS>, cudaFuncAttributeMaxDynamicSharedMemorySize, GEMM_SMEM);
    cudaFuncSetAttribute(hgemm_kernel<1>,     cudaFuncAttributeMaxDynamicSharedMemorySize, GEMM_SMEM);

    // ---- layer 1 front half (keeps hgemm early for ncu window) ----
    {
        int na = NN * INC;
        split_kernel<<<(na + 255) / 256, 256>>>(x, B.ah, B.al, na);
    }
    run_gemm<HEADS>(INC, W1, a1_src, a1_dst, B);

    // ---- CSR build ----
    zero_int2_kernel<<<(NN + 255) / 256, 256>>>(B.deg, B.cur, NN);
    count_kernel<<<(ETOT + 255) / 256, 256>>>(ei, B.deg);
    scan_kernel<<<1, SCAN_T>>>(B.deg, B.rowptr);
    scatter_kernel<<<(ETOT + 255) / 256, 256>>>(ei, B.rowptr, B.cur, B.esrc);

    aggregate4_kernel<<<(NN * 32 + 255) / 256, 256>>>(
        B.rowptr, B.esrc, B.asrc, B.adst, B.hlin, b1, B.ah, B.al);

    run_gemm<HEADS>(FMAX, W2, a2_src, a2_dst, B);
    aggregate4_kernel<<<(NN * 32 + 255) / 256, 256>>>(
        B.rowptr, B.esrc, B.asrc, B.adst, B.hlin, b2, B.ah, B.al);

    run_gemm<1>(FMAX, W3, a3_src, a3_dst, B);
    aggregate1_kernel<<<(NN * 32 + 255) / 256, 256>>>(
        B.rowptr, B.esrc, B.asrc, B.adst, B.hlin, b3, (float*)d_out);
}

// round 17
// speedup vs baseline: 1.4963x; 1.2303x over previous
#include <cuda_runtime.h>
#include <cuda_bf16.h>
#include <cuda_fp16.h>
#include <math.h>
#include <stdint.h>

// Problem constants
#define NN     20000
#define EE     400000
#define ETOT   420000
#define INC    768
#define HID    128
#define HEADS  4
#define FMAX   512

// ---------------- device scratch ----------------
__device__ __half g_hlin[(size_t)NN * FMAX];
__device__ float g_asrc[(size_t)NN * HEADS];
__device__ float g_adst[(size_t)NN * HEADS];
__device__ __half g_ah [(size_t)NN * INC];     // A (fp16)
__device__ __half g_wth[(size_t)FMAX * INC];   // W^T (fp16)
__device__ int g_deg[NN];
__device__ int g_cur[NN];
__device__ int g_rowptr[NN + 1];
__device__ int g_esrc[ETOT];

// ---------------- misc helpers ----------------
__device__ __forceinline__ int clampN(int v) { return v < 0 ? 0 : (v >= NN ? NN - 1 : v); }
__device__ __forceinline__ uint32_t smem_u32(const void* p) {
    uint32_t a;
    asm("{ .reg .u64 t; cvta.to.shared.u64 t, %1; cvt.u32.u64 %0, t; }" : "=r"(a) : "l"(p));
    return a;
}

__global__ void zero_int2_kernel(int* __restrict__ a, int* __restrict__ b, int n) {
    int i = blockIdx.x * blockDim.x + threadIdx.x;
    if (i < n) { a[i] = 0; b[i] = 0; }
}

// ---------------- CSR build ----------------
__global__ void count_kernel(const int* __restrict__ ei, int* __restrict__ deg) {
    int e = blockIdx.x * blockDim.x + threadIdx.x;
    if (e >= ETOT) return;
    int d = (e < EE) ? clampN(ei[EE + e]) : e - EE;
    atomicAdd(&deg[d], 1);
}

#define SCAN_T 1024
#define SCAN_CH 20
__global__ void scan_kernel(const int* __restrict__ deg, int* __restrict__ rowptr) {
    __shared__ int sums[SCAN_T];
    int t = threadIdx.x;
    int base = t * SCAN_CH;
    int local = 0;
#pragma unroll
    for (int i = 0; i < SCAN_CH; i++) {
        int idx = base + i;
        if (idx < NN) local += deg[idx];
    }
    sums[t] = local;
    __syncthreads();
    for (int off = 1; off < SCAN_T; off <<= 1) {
        int v = (t >= off) ? sums[t - off] : 0;
        __syncthreads();
        sums[t] += v;
        __syncthreads();
    }
    int run = sums[t] - local;
#pragma unroll
    for (int i = 0; i < SCAN_CH; i++) {
        int idx = base + i;
        if (idx < NN) { rowptr[idx] = run; run += deg[idx]; }
    }
    if (t == SCAN_T - 1) rowptr[NN] = sums[SCAN_T - 1];
}

__global__ void scatter_kernel(const int* __restrict__ ei,
                               const int* __restrict__ rowptr,
                               int* __restrict__ cur, int* __restrict__ esrc) {
    int e = blockIdx.x * blockDim.x + threadIdx.x;
    if (e >= ETOT) return;
    int s, d;
    if (e < EE) { s = clampN(ei[e]); d = clampN(ei[EE + e]); } else { s = d = e - EE; }
    int pos = rowptr[d] + atomicAdd(&cur[d], 1);
    esrc[pos] = s;
}

// ---------------- fp32 -> fp16 convert (x only) ----------------
__global__ void split_kernel(const float* __restrict__ x,
                             __half* __restrict__ hi, int n) {
    int i = blockIdx.x * blockDim.x + threadIdx.x;
    if (i >= n) return;
    hi[i] = __float2half_rn(x[i]);
}

// W [K,N] fp32 -> Wt [N,K] fp16 via smem-tiled transpose
__global__ void splitT_kernel(const float* __restrict__ W,
                              __half* __restrict__ hi, int K, int Nn) {
    __shared__ float t[32][33];
    const int tx = threadIdx.x;
    const int ty = threadIdx.y;
    const int n0 = blockIdx.x * 32;
    const int k0 = blockIdx.y * 32;
#pragma unroll
    for (int i = 0; i < 4; i++) {
        int k = k0 + ty + i * 8;
        t[ty + i * 8][tx] = W[(size_t)k * Nn + n0 + tx];
    }
    __syncthreads();
#pragma unroll
    for (int i = 0; i < 4; i++) {
        int n = n0 + ty + i * 8;
        hi[(size_t)n * K + k0 + tx] = __float2half_rn(t[tx][ty + i * 8]);
    }
}

// ---------------- HMMA fp16 GEMM: single product A*B^T ----------------------
// BK=32, 2-stage cp.async, 2 tiles per stage (A, B). SPAD=40 conflict-free.
#define SPAD 40
#define TILE_ELEMS (128 * SPAD)
#define STAGE_ELEMS (2 * TILE_ELEMS)
#define GEMM_SMEM (2 * STAGE_ELEMS * 2)   // 40960 bytes

__device__ __forceinline__ void mma_f16(float* c, const uint32_t* a, const uint32_t* b) {
    asm volatile("mma.sync.aligned.m16n8k16.row.col.f32.f16.f16.f32 "
                 "{%0,%1,%2,%3}, {%4,%5,%6,%7}, {%8,%9}, {%0,%1,%2,%3};"
                 : "+f"(c[0]), "+f"(c[1]), "+f"(c[2]), "+f"(c[3])
                 : "r"(a[0]), "r"(a[1]), "r"(a[2]), "r"(a[3]),
                   "r"(b[0]), "r"(b[1]));
}
#define LDM_X4(r0, r1, r2, r3, a) \
    asm volatile("ldmatrix.sync.aligned.m8n8.x4.shared.b16 {%0,%1,%2,%3}, [%4];" \
                 : "=r"(r0), "=r"(r1), "=r"(r2), "=r"(r3) : "r"(a))
#define CP_ASYNC16(dst, src) \
    asm volatile("cp.async.ca.shared.global [%0], [%1], 16;" :: "r"(dst), "l"(src))

template <int H>
__global__ void __launch_bounds__(256)
hgemm_kernel(const __half* __restrict__ Ah,
             const __half* __restrict__ Bh,
             __half* __restrict__ C,
             const float* __restrict__ avec_src,
             const float* __restrict__ avec_dst,
             float* __restrict__ asrc,
             float* __restrict__ adst,
             int M, int K, int Nn) {
    extern __shared__ __half sm[];

    const int tid  = threadIdx.x;
    const int lane = tid & 31;
    const int wid  = tid >> 5;
    const int wm   = (wid >> 2) * 64;
    const int wn   = (wid & 3) * 32;
    const int row0 = blockIdx.y * 128;
    const int col0 = blockIdx.x * 128;
    const int g4   = lane >> 2;
    const int t4   = lane & 3;

    const int a_off = (lane & 15) * SPAD + (lane >> 4) * 8;
    const int b_off = ((lane & 7) + ((lane & 16) ? 8 : 0)) * SPAD + ((lane & 8) ? 8 : 0);

    const int lr = tid >> 1;
    const int lc = (tid & 1) * 16;

    float acc[4][4][4];
#pragma unroll
    for (int a = 0; a < 4; a++)
#pragma unroll
        for (int b = 0; b < 4; b++)
#pragma unroll
            for (int c = 0; c < 4; c++) acc[a][b][c] = 0.f;

    const int nCh = K >> 5;
    const int gra = min(row0 + lr, M - 1);
    const int grb = col0 + lr;
    const uint32_t smb = smem_u32(sm);

#define ISSUE(ch) do {                                                          \
    uint32_t sb_ = smb + (uint32_t)((ch) & 1) * (STAGE_ELEMS * 2);              \
    int kc0_ = (ch) << 5;                                                       \
    uint32_t d_ = sb_ + (uint32_t)(lr * SPAD + lc) * 2;                         \
    const __half* pa_ = Ah + (size_t)gra * K + kc0_ + lc;                       \
    const __half* pc_ = Bh + (size_t)grb * K + kc0_ + lc;                       \
    CP_ASYNC16(d_ + 0 * TILE_ELEMS * 2,      pa_);                              \
    CP_ASYNC16(d_ + 0 * TILE_ELEMS * 2 + 16, pa_ + 8);                          \
    CP_ASYNC16(d_ + 1 * TILE_ELEMS * 2,      pc_);                              \
    CP_ASYNC16(d_ + 1 * TILE_ELEMS * 2 + 16, pc_ + 8);                          \
    asm volatile("cp.async.commit_group;");                                     \
} while (0)

    ISSUE(0);
    for (int ch = 0; ch < nCh; ch++) {
        if (ch + 1 < nCh) {
            ISSUE(ch + 1);
            asm volatile("cp.async.wait_group 1;");
        } else {
            asm volatile("cp.async.wait_group 0;");
        }
        __syncthreads();

        const uint32_t bAh = smb + (uint32_t)(ch & 1) * (STAGE_ELEMS * 2);
        const uint32_t bBh = bAh + TILE_ELEMS * 2;

#pragma unroll
        for (int ks = 0; ks < 32; ks += 16) {
            uint32_t bh[4][2];
#pragma unroll
            for (int ntp = 0; ntp < 2; ntp++) {
                uint32_t off = (uint32_t)((wn + ntp * 16) * SPAD + ks + b_off) * 2;
                LDM_X4(bh[2 * ntp][0], bh[2 * ntp][1], bh[2 * ntp + 1][0], bh[2 * ntp + 1][1], bBh + off);
            }
#pragma unroll
            for (int mt = 0; mt < 4; mt++) {
                uint32_t off = (uint32_t)((wm + mt * 16) * SPAD + ks + a_off) * 2;
                uint32_t ah[4];
                LDM_X4(ah[0], ah[1], ah[2], ah[3], bAh + off);
#pragma unroll
                for (int nt = 0; nt < 4; nt++) {
                    mma_f16(acc[mt][nt], ah, bh[nt]);
                }
            }
        }
        __syncthreads();
    }
#undef ISSUE

    // ---- epilogue: store C (fp16) + attention dots via SMEM reduction ------
    const int h = col0 >> 7;
    float vs[4][2], vd[4][2];
#pragma unroll
    for (int nt = 0; nt < 4; nt++) {
        int gc = col0 + wn + nt * 8 + t4 * 2;
#pragma unroll
        for (int j = 0; j < 2; j++) {
            vs[nt][j] = avec_src[gc + j];
            vd[nt][j] = avec_dst[gc + j];
        }
    }

    float* s_red = (float*)sm;   // 256 floats
    __syncthreads();
    if (tid < 256) s_red[tid] = 0.f;
    __syncthreads();

#pragma unroll
    for (int mt = 0; mt < 4; mt++) {
        float ps0 = 0.f, pd0 = 0.f, ps1 = 0.f, pd1 = 0.f;
#pragma unroll
        for (int nt = 0; nt < 4; nt++) {
            int gm = row0 + wm + mt * 16 + g4;
            int gc = col0 + wn + nt * 8 + t4 * 2;
            if (gm < M)
                *(__half2*)&C[(size_t)gm * Nn + gc] =
                    __floats2half2_rn(acc[mt][nt][0], acc[mt][nt][1]);
            if (gm + 8 < M)
                *(__half2*)&C[(size_t)(gm + 8) * Nn + gc] =
                    __floats2half2_rn(acc[mt][nt][2], acc[mt][nt][3]);
            ps0 = fmaf(acc[mt][nt][0], vs[nt][0], fmaf(acc[mt][nt][1], vs[nt][1], ps0));
            pd0 = fmaf(acc[mt][nt][0], vd[nt][0], fmaf(acc[mt][nt][1], vd[nt][1], pd0));
            ps1 = fmaf(acc[mt][nt][2], vs[nt][0], fmaf(acc[mt][nt][3], vs[nt][1], ps1));
            pd1 = fmaf(acc[mt][nt][2], vd[nt][0], fmaf(acc[mt][nt][3], vd[nt][1], pd1));
        }
#pragma unroll
        for (int o = 1; o <= 2; o <<= 1) {
            ps0 += __shfl_xor_sync(0xffffffffu, ps0, o);
            pd0 += __shfl_xor_sync(0xffffffffu, pd0, o);
            ps1 += __shfl_xor_sync(0xffffffffu, ps1, o);
            pd1 += __shfl_xor_sync(0xffffffffu, pd1, o);
        }
        if (t4 == 0) {
            int r = wm + mt * 16 + g4;
            atomicAdd(&s_red[r],           ps0);
            atomicAdd(&s_red[128 + r],     pd0);
            atomicAdd(&s_red[r + 8],       ps1);
            atomicAdd(&s_red[128 + r + 8], pd1);
        }
    }
    __syncthreads();
    if (tid < 128) {
        int gm = row0 + tid;
        if (gm < M) {
            asrc[(size_t)gm * H + h] = s_red[tid];
            adst[(size_t)gm * H + h] = s_red[128 + tid];
        }
    }
}

// ---------------- fused aggregate, H=4: one warp per NODE (all heads) -------
__global__ void aggregate4_kernel(const int* __restrict__ rowptr,
                                  const int* __restrict__ esrc,
                                  const float* __restrict__ asrc,
                                  const float* __restrict__ adst,
                                  const __half* __restrict__ hlin,
                                  const float* __restrict__ bias,
                                  __half* __restrict__ hi) {
    int n = (blockIdx.x * blockDim.x + threadIdx.x) >> 5;
    int lane = threadIdx.x & 31;
    if (n >= NN) return;
    float4 ad = *(const float4*)&adst[(size_t)n * 4];
    int beg = rowptr[n], end = rowptr[n + 1];

    float4 acc0 = {0,0,0,0}, acc1 = {0,0,0,0}, acc2 = {0,0,0,0}, acc3 = {0,0,0,0};
    float4 ss = {0,0,0,0};

    for (int base = beg; base < end; base += 32) {
        int j = base + lane;
        float4 vj = {0,0,0,0};
        int sj = 0;
        if (j < end) {
            sj = esrc[j];
            float4 as = *(const float4*)&asrc[(size_t)sj * 4];
            float e0 = as.x + ad.x, e1 = as.y + ad.y, e2 = as.z + ad.z, e3 = as.w + ad.w;
            e0 = (e0 > 0.f) ? e0 : 0.2f * e0;
            e1 = (e1 > 0.f) ? e1 : 0.2f * e1;
            e2 = (e2 > 0.f) ? e2 : 0.2f * e2;
            e3 = (e3 > 0.f) ? e3 : 0.2f * e3;
            vj.x = __expf(e0); vj.y = __expf(e1); vj.z = __expf(e2); vj.w = __expf(e3);
        }
        int cnt = min(32, end - base);
        for (int t = 0; t < cnt; t++) {
            int s   = __shfl_sync(0xffffffffu, sj, t);
            float w0 = __shfl_sync(0xffffffffu, vj.x, t);
            float w1 = __shfl_sync(0xffffffffu, vj.y, t);
            float w2 = __shfl_sync(0xffffffffu, vj.z, t);
            float w3 = __shfl_sync(0xffffffffu, vj.w, t);
            const uint2* p = (const uint2*)(hlin + (size_t)s * FMAX);
            uint2 u0 = p[lane];
            uint2 u1 = p[lane + 32];
            uint2 u2 = p[lane + 64];
            uint2 u3 = p[lane + 96];
            float2 a0 = __half22float2(*(const __half2*)&u0.x);
            float2 b0 = __half22float2(*(const __half2*)&u0.y);
            float2 a1 = __half22float2(*(const __half2*)&u1.x);
            float2 b1 = __half22float2(*(const __half2*)&u1.y);
            float2 a2 = __half22float2(*(const __half2*)&u2.x);
            float2 b2 = __half22float2(*(const __half2*)&u2.y);
            float2 a3 = __half22float2(*(const __half2*)&u3.x);
            float2 b3 = __half22float2(*(const __half2*)&u3.y);
            acc0.x = fmaf(w0, a0.x, acc0.x); acc0.y = fmaf(w0, a0.y, acc0.y);
            acc0.z = fmaf(w0, b0.x, acc0.z); acc0.w = fmaf(w0, b0.y, acc0.w);
            acc1.x = fmaf(w1, a1.x, acc1.x); acc1.y = fmaf(w1, a1.y, acc1.y);
            acc1.z = fmaf(w1, b1.x, acc1.z); acc1.w = fmaf(w1, b1.y, acc1.w);
            acc2.x = fmaf(w2, a2.x, acc2.x); acc2.y = fmaf(w2, a2.y, acc2.y);
            acc2.z = fmaf(w2, b2.x, acc2.z); acc2.w = fmaf(w2, b2.y, acc2.w);
            acc3.x = fmaf(w3, a3.x, acc3.x); acc3.y = fmaf(w3, a3.y, acc3.y);
            acc3.z = fmaf(w3, b3.x, acc3.z); acc3.w = fmaf(w3, b3.y, acc3.w);
            ss.x += w0; ss.y += w1; ss.z += w2; ss.w += w3;
        }
    }

#define FIN(acch, sh, hh) do {                                                  \
    float inv = 1.f / ((sh) + 1e-16f);                                          \
    float4 bv = *(const float4*)&bias[(hh) * HID + lane * 4];                   \
    float4 o;                                                                   \
    o.x = (acch).x * inv + bv.x;                                                \
    o.y = (acch).y * inv + bv.y;                                                \
    o.z = (acch).z * inv + bv.z;                                                \
    o.w = (acch).w * inv + bv.w;                                                \
    o.x = (o.x > 0.f) ? o.x : expm1f(o.x);                                      \
    o.y = (o.y > 0.f) ? o.y : expm1f(o.y);                                      \
    o.z = (o.z > 0.f) ? o.z : expm1f(o.z);                                      \
    o.w = (o.w > 0.f) ? o.w : expm1f(o.w);                                      \
    size_t off = ((size_t)n * 4 + (hh)) * HID + lane * 4;                       \
    __half2 p0 = __floats2half2_rn(o.x, o.y);                                   \
    __half2 p1 = __floats2half2_rn(o.z, o.w);                                   \
    *(__half2*)&hi[off + 0] = p0;                                               \
    *(__half2*)&hi[off + 2] = p1;                                               \
} while (0)

    FIN(acc0, ss.x, 0);
    FIN(acc1, ss.y, 1);
    FIN(acc2, ss.z, 2);
    FIN(acc3, ss.w, 3);
#undef FIN
}

// ---------------- fused aggregate H=1 (layer 3, fp32 out) -------------------
__global__ void aggregate1_kernel(const int* __restrict__ rowptr,
                                  const int* __restrict__ esrc,
                                  const float* __restrict__ asrc,
                                  const float* __restrict__ adst,
                                  const __half* __restrict__ hlin,
                                  const float* __restrict__ bias,
                                  float* __restrict__ out) {
    int n = (blockIdx.x * blockDim.x + threadIdx.x) >> 5;
    int lane = threadIdx.x & 31;
    if (n >= NN) return;
    float adn = adst[n];
    int beg = rowptr[n], end = rowptr[n + 1];

    float4 acc = {0,0,0,0};
    float ssum = 0.f;

    for (int base = beg; base < end; base += 32) {
        int j = base + lane;
        float vj = 0.f;
        int sj = 0;
        if (j < end) {
            sj = esrc[j];
            float v = asrc[sj] + adn;
            v = (v > 0.f) ? v : 0.2f * v;
            vj = __expf(v);
        }
        int cnt = min(32, end - base);
        for (int t = 0; t < cnt; t++) {
            float v = __shfl_sync(0xffffffffu, vj, t);
            int s   = __shfl_sync(0xffffffffu, sj, t);
            const uint2* hp = (const uint2*)(hlin + (size_t)s * HID);
            uint2 u = hp[lane];
            float2 f0 = __half22float2(*(const __half2*)&u.x);
            float2 f1 = __half22float2(*(const __half2*)&u.y);
            acc.x = fmaf(v, f0.x, acc.x);
            acc.y = fmaf(v, f0.y, acc.y);
            acc.z = fmaf(v, f1.x, acc.z);
            acc.w = fmaf(v, f1.y, acc.w);
            ssum += v;
        }
    }
    float inv = 1.f / (ssum + 1e-16f);
    float4 bv = *(const float4*)&bias[lane * 4];
    float4 o;
    o.x = acc.x * inv + bv.x;
    o.y = acc.y * inv + bv.y;
    o.z = acc.z * inv + bv.z;
    o.w = acc.w * inv + bv.w;
    *(float4*)&out[(size_t)n * HID + lane * 4] = o;
}

// ---------------- host orchestration ----------------
struct Buffers {
    __half* hlin;
    float *asrc, *adst;
    __half *ah, *wth;
    int *deg, *cur, *rowptr, *esrc;
};

template <int H>
static void run_gemm(int K, const float* W, const float* a_src, const float* a_dst,
                     const Buffers& B) {
    const int F = H * HID;
    dim3 tgrid(F / 32, K / 32);
    splitT_kernel<<<tgrid, dim3(32, 8)>>>(W, B.wth, K, F);
    dim3 grid(F / 128, (NN + 127) / 128);
    hgemm_kernel<H><<<grid, 256, GEMM_SMEM>>>(B.ah, B.wth, B.hlin,
                                              a_src, a_dst, B.asrc, B.adst, NN, K, F);
}

extern "C" void kernel_launch(void* const* d_in, const int* in_sizes, int n_in,
                              void* d_out, int out_size) {
    const float* x       = (const float*)d_in[0];
    const int*   ei      = (const int*)d_in[1];
    const float* W1      = (const float*)d_in[2];
    const float* a1_src  = (const float*)d_in[3];
    const float* a1_dst  = (const float*)d_in[4];
    const float* b1      = (const float*)d_in[5];
    const float* W2      = (const float*)d_in[6];
    const float* a2_src  = (const float*)d_in[7];
    const float* a2_dst  = (const float*)d_in[8];
    const float* b2      = (const float*)d_in[9];
    const float* W3      = (const float*)d_in[10];
    const float* a3_src  = (const float*)d_in[11];
    const float* a3_dst  = (const float*)d_in[12];
    const float* b3      = (const float*)d_in[13];

    Buffers B;
    cudaGetSymbolAddress((void**)&B.hlin,   g_hlin);
    cudaGetSymbolAddress((void**)&B.asrc,   g_asrc);
    cudaGetSymbolAddress((void**)&B.adst,   g_adst);
    cudaGetSymbolAddress((void**)&B.ah,     g_ah);
    cudaGetSymbolAddress((void**)&B.wth,    g_wth);
    cudaGetSymbolAddress((void**)&B.deg,    g_deg);
    cudaGetSymbolAddress((void**)&B.cur,    g_cur);
    cudaGetSymbolAddress((void**)&B.rowptr, g_rowptr);
    cudaGetSymbolAddress((void**)&B.esrc,   g_esrc);

    cudaFuncSetAttribute(hgemm_kernel<HEADS>, cudaFuncAttributeMaxDynamicSharedMemorySize, GEMM_SMEM);
    cudaFuncSetAttribute(hgemm_kernel<1>,     cudaFuncAttributeMaxDynamicSharedMemorySize, GEMM_SMEM);

    // ---- layer 1 front half (keeps hgemm early for ncu window) ----
    {
        int na = NN * INC;
        split_kernel<<<(na + 255) / 256, 256>>>(x, B.ah, na);
    }
    run_gemm<HEADS>(INC, W1, a1_src, a1_dst, B);

    // ---- CSR build ----
    zero_int2_kernel<<<(NN + 255) / 256, 256>>>(B.deg, B.cur, NN);
    count_kernel<<<(ETOT + 255) / 256, 256>>>(ei, B.deg);
    scan_kernel<<<1, SCAN_T>>>(B.deg, B.rowptr);
    scatter_kernel<<<(ETOT + 255) / 256, 256>>>(ei, B.rowptr, B.cur, B.esrc);

    aggregate4_kernel<<<(NN * 32 + 255) / 256, 256>>>(
        B.rowptr, B.esrc, B.asrc, B.adst, B.hlin, b1, B.ah);

    run_gemm<HEADS>(FMAX, W2, a2_src, a2_dst, B);
    aggregate4_kernel<<<(NN * 32 + 255) / 256, 256>>>(
        B.rowptr, B.esrc, B.asrc, B.adst, B.hlin, b2, B.ah);

    run_gemm<1>(FMAX, W3, a3_src, a3_dst, B);
    aggregate1_kernel<<<(NN * 32 + 255) / 256, 256>>>(
        B.rowptr, B.esrc, B.asrc, B.adst, B.hlin, b3, (float*)d_out);
}